// round 1
// baseline (speedup 1.0000x reference)
#include <cuda_runtime.h>
#include <cstdint>
#include <math.h>

// ----------------------------------------------------------------------------
// DenseCRF mean-field with permutohedral lattice filtering, full GPU pipeline.
// Bilateral lattice: d=5 (x/80, y/80, r/13, g/13, b/13), spatial: d=2 (x/3,y/3)
// 5 mean-field iterations, C=21 classes, 320x320 image.
// ----------------------------------------------------------------------------

#define HH 320
#define WW 320
#define NPIX (HH*WW)                 // 102400
#define NC 21
#define DBIL 5
#define DSP 2
#define MBIL (NPIX*(DBIL+1))         // 614400 worst-case unique lattice pts
#define MSP  (NPIX*(DSP+1))          // 307200
#define HBSZ (1u<<21)                // bilateral hash capacity (load ~0.29)
#define HSSZ (1u<<20)
#define EMPTYK 0xFFFFFFFFFFFFFFFFULL

struct Globals {
    unsigned long long hkeyB[HBSZ];
    int                hidxB[HBSZ];
    unsigned long long hkeyS[HSSZ];
    int                hidxS[HSSZ];
    int countB, countS;
    unsigned long long ukeyB[MBIL];
    unsigned long long ukeyS[MSP];
    unsigned long long pkB[NPIX*(DBIL+1)];
    unsigned long long pkS[NPIX*(DSP+1)];
    int   osB[NPIX*(DBIL+1)];
    float wsB[NPIX*(DBIL+1)];
    int   osS[NPIX*(DSP+1)];
    float wsS[NPIX*(DSP+1)];
    int n1B[(DBIL+1)*MBIL];
    int n2B[(DBIL+1)*MBIL];
    int n1S[(DSP+1)*MSP];
    int n2S[(DSP+1)*MSP];
    float bufB0[(long long)MBIL*NC];
    float bufB1[(long long)MBIL*NC];
    float bufS0[(long long)MSP*NC];
    float bufS1[(long long)MSP*NC];
    float nbuf0[MBIL];
    float nbuf1[MBIL];
    float normB[NPIX];
    float normS[NPIX];
    float Q[NPIX*NC];
    float msg[NPIX*NC];
};
__device__ Globals G;

// ---------------- lattice selectors (compile-time) --------------------------
template<int D> __device__ __forceinline__ unsigned long long* HK()   { return (D==DBIL)? G.hkeyB : G.hkeyS; }
template<int D> __device__ __forceinline__ int*                HI()   { return (D==DBIL)? G.hidxB : G.hidxS; }
template<int D> __device__ __forceinline__ int*                CNT()  { return (D==DBIL)? &G.countB : &G.countS; }
template<int D> __device__ __forceinline__ unsigned long long* UK()   { return (D==DBIL)? G.ukeyB : G.ukeyS; }
template<int D> __device__ __forceinline__ unsigned long long* PK()   { return (D==DBIL)? G.pkB : G.pkS; }
template<int D> __device__ __forceinline__ int*                OS()   { return (D==DBIL)? G.osB : G.osS; }
template<int D> __device__ __forceinline__ float*              WSp()  { return (D==DBIL)? G.wsB : G.wsS; }
template<int D> __device__ __forceinline__ int*                N1()   { return (D==DBIL)? G.n1B : G.n1S; }
template<int D> __device__ __forceinline__ int*                N2()   { return (D==DBIL)? G.n2B : G.n2S; }
template<int D> __device__ __forceinline__ float*              BUFP(int p){
    if (D==DBIL) return p ? G.bufB1 : G.bufB0;
    else         return p ? G.bufS1 : G.bufS0;
}
template<int D> __host__ __device__ constexpr unsigned int HMSK(){ return (D==DBIL)? (HBSZ-1u) : (HSSZ-1u); }
template<int D> __host__ __device__ constexpr unsigned int HSZ (){ return (D==DBIL)? HBSZ : HSSZ; }
template<int D> __host__ __device__ constexpr int          MMAX(){ return (D==DBIL)? MBIL : MSP; }

// ---------------- hash ------------------------------------------------------
__device__ __forceinline__ unsigned int hmix(unsigned long long x, unsigned int mask){
    x ^= x >> 33; x *= 0xff51afd7ed558ccdULL;
    x ^= x >> 33; x *= 0xc4ceb9fe1a85ec53ULL;
    x ^= x >> 33;
    return (unsigned int)x & mask;
}
__device__ __forceinline__ void hinsert(unsigned long long* hk, unsigned int mask, unsigned long long key){
    unsigned int s = hmix(key, mask);
    while (true){
        unsigned long long prev = atomicCAS(&hk[s], EMPTYK, key);
        if (prev == EMPTYK || prev == key) return;
        s = (s+1) & mask;
    }
}
__device__ __forceinline__ int hlookup(const unsigned long long* hk, const int* hi,
                                       unsigned int mask, unsigned long long key){
    unsigned int s = hmix(key, mask);
    while (true){
        unsigned long long k = hk[s];
        if (k == key)    return hi[s];
        if (k == EMPTYK) return -1;
        s = (s+1) & mask;
    }
}

// ---------------- kernels ---------------------------------------------------
template<int D>
__global__ void initHashK(){
    unsigned int s = blockIdx.x*blockDim.x + threadIdx.x;
    if (s < HSZ<D>()) HK<D>()[s] = EMPTYK;
    if (s == 0) *CNT<D>() = 0;
}

// per-pixel simplex: barycentric weights + packed keys; claim keys in hash
template<int D>
__global__ void buildK(const float* __restrict__ image){
    int i = blockIdx.x*blockDim.x + threadIdx.x;
    if (i >= NPIX) return;
    float f[D];
    float x = (float)(i % WW), y = (float)(i / WW);
    if constexpr (D == DBIL){
        f[0] = x / 80.0f;  f[1] = y / 80.0f;
        f[2] = image[i*3+0] / 13.0f;
        f[3] = image[i*3+1] / 13.0f;
        f[4] = image[i*3+2] / 13.0f;
    } else {
        f[0] = x / 3.0f;   f[1] = y / 3.0f;
    }
    float cf[D];
    #pragma unroll
    for (int k=0;k<D;k++){
        double sc = sqrt(2.0/3.0) * (double)(D+1) / sqrt((double)((k+1)*(k+2)));
        cf[k] = f[k] * (float)sc;
    }
    float suf[D];
    { float s=0.f; for (int k=D-1;k>=0;k--){ s += cf[k]; suf[k]=s; } }
    float el[D+1];
    el[0] = suf[0];
    #pragma unroll
    for (int k=1;k<=D;k++){
        float t = (k<D) ? suf[k] : 0.0f;
        el[k] = t - (float)k * cf[k-1];
    }
    const float down = 1.0f/(float)(D+1);
    float rem0[D+1]; int rank[D+1]; int ssum=0;
    #pragma unroll
    for (int k=0;k<=D;k++){
        float rd = rintf(el[k]*down);
        rem0[k] = rd * (float)(D+1);
        ssum += (int)rd;
    }
    float diff[D+1];
    #pragma unroll
    for (int k=0;k<=D;k++) diff[k] = el[k] - rem0[k];
    #pragma unroll
    for (int a=0;a<=D;a++){
        int r = 0;
        #pragma unroll
        for (int b=0;b<=D;b++)
            if (diff[b] > diff[a] || (diff[b] == diff[a] && b < a)) r++;
        rank[a] = r + ssum;
    }
    #pragma unroll
    for (int k=0;k<=D;k++){
        if (rank[k] < 0)      { rank[k] += D+1; rem0[k] += (float)(D+1); }
        else if (rank[k] > D) { rank[k] -= D+1; rem0[k] -= (float)(D+1); }
    }
    float bb[D+2];
    #pragma unroll
    for (int k=0;k<D+2;k++) bb[k]=0.f;
    #pragma unroll
    for (int k=0;k<=D;k++){
        float v = (el[k]-rem0[k]) * down;
        bb[D   - rank[k]] += v;
        bb[D+1 - rank[k]] -= v;
    }
    bb[0] += 1.0f + bb[D+1];
    int key0[D];
    #pragma unroll
    for (int k=0;k<D;k++) key0[k] = (int)lrintf(rem0[k]);
    unsigned long long* hk = HK<D>();
    const unsigned int mask = HMSK<D>();
    #pragma unroll
    for (int r=0;r<=D;r++){
        unsigned long long pk = 0;
        #pragma unroll
        for (int k=0;k<D;k++){
            int canon = (rank[k] < D+1-r) ? r : r-(D+1);
            pk |= ((unsigned long long)(unsigned int)(key0[k]+canon+2048) & 0xFFFULL) << (12*k);
        }
        WSp<D>()[i*(D+1)+r] = bb[r];
        PK<D>()[i*(D+1)+r]  = pk;
        hinsert(hk, mask, pk);
    }
}

template<int D>
__global__ void assignK(){
    unsigned int s = blockIdx.x*blockDim.x + threadIdx.x;
    if (s >= HSZ<D>()) return;
    unsigned long long k = HK<D>()[s];
    if (k != EMPTYK){
        int idx = atomicAdd(CNT<D>(), 1);
        HI<D>()[s] = idx;
        UK<D>()[idx] = k;
    }
}

template<int D>
__global__ void osK(){
    int tid = blockIdx.x*blockDim.x + threadIdx.x;
    if (tid >= NPIX*(D+1)) return;
    OS<D>()[tid] = hlookup(HK<D>(), HI<D>(), HMSK<D>(), PK<D>()[tid]);
}

template<int D>
__global__ void neighK(){
    int m = blockIdx.x*blockDim.x + threadIdx.x;
    if (m >= *CNT<D>()) return;
    unsigned long long k = UK<D>()[m];
    int c[D];
    #pragma unroll
    for (int t=0;t<D;t++) c[t] = (int)((k >> (12*t)) & 0xFFF) - 2048;
    unsigned long long* hk = HK<D>(); int* hi = HI<D>();
    const unsigned int mask = HMSK<D>();
    #pragma unroll
    for (int j=0;j<=D;j++){
        unsigned long long p1=0, p2=0;
        #pragma unroll
        for (int t=0;t<D;t++){
            int a1 = c[t]-1 + ((t==j)?(D+1):0);
            int a2 = c[t]+1 - ((t==j)?(D+1):0);
            p1 |= ((unsigned long long)(unsigned int)(a1+2048) & 0xFFFULL) << (12*t);
            p2 |= ((unsigned long long)(unsigned int)(a2+2048) & 0xFFFULL) << (12*t);
        }
        N1<D>()[j*MMAX<D>()+m] = hlookup(hk, hi, mask, p1);
        N2<D>()[j*MMAX<D>()+m] = hlookup(hk, hi, mask, p2);
    }
}

template<int D>
__global__ void zeroBufK(){
    long long tid = (long long)blockIdx.x*blockDim.x + threadIdx.x;
    long long n = (long long)(*CNT<D>()) * NC;
    if (tid < n) BUFP<D>(0)[tid] = 0.f;
}
template<int D>
__global__ void zeroNK(){
    int tid = blockIdx.x*blockDim.x + threadIdx.x;
    if (tid < *CNT<D>()) G.nbuf0[tid] = 0.f;
}

template<int D>
__global__ void splatK(){
    int tid = blockIdx.x*blockDim.x + threadIdx.x;
    if (tid >= NPIX*NC) return;
    int i = tid / NC, c = tid % NC;
    float v = G.Q[tid];
    const int*   os = OS<D>();
    const float* ws = WSp<D>();
    float* buf = BUFP<D>(0);
    #pragma unroll
    for (int j=0;j<=D;j++){
        atomicAdd(&buf[(long long)os[i*(D+1)+j]*NC + c], ws[i*(D+1)+j]*v);
    }
}
template<int D>
__global__ void splatNK(){
    int i = blockIdx.x*blockDim.x + threadIdx.x;
    if (i >= NPIX) return;
    const int* os = OS<D>(); const float* ws = WSp<D>();
    #pragma unroll
    for (int j=0;j<=D;j++)
        atomicAdd(&G.nbuf0[os[i*(D+1)+j]], ws[i*(D+1)+j]);
}

// one blur pass: out[m] = in[m] + 0.5*(in[n1[j][m]] + in[n2[j][m]]), missing -> 0
template<int D, int C>
__global__ void blurK(int j, int p){
    long long tid = (long long)blockIdx.x*blockDim.x + threadIdx.x;
    int M = *CNT<D>();
    int m, c;
    if (C == 1){ m = (int)tid; c = 0; }
    else       { m = (int)(tid / C); c = (int)(tid % C); }
    if (m >= M) return;
    const float* in; float* out;
    if (C == 1){ in = p ? G.nbuf1 : G.nbuf0; out = p ? G.nbuf0 : G.nbuf1; }
    else       { in = BUFP<D>(p);            out = BUFP<D>(1-p); }
    int a = N1<D>()[j*MMAX<D>()+m];
    int b = N2<D>()[j*MMAX<D>()+m];
    float va = (a >= 0) ? in[(long long)a*C + c] : 0.f;
    float vb = (b >= 0) ? in[(long long)b*C + c] : 0.f;
    out[(long long)m*C + c] = in[(long long)m*C + c] + 0.5f*(va + vb);
}

template<int D, bool ACC>
__global__ void sliceK(float wgt, int p){
    int tid = blockIdx.x*blockDim.x + threadIdx.x;
    if (tid >= NPIX*NC) return;
    int i = tid / NC, c = tid % NC;
    const int*   os  = OS<D>();
    const float* ws  = WSp<D>();
    const float* buf = BUFP<D>(p);
    float s = 0.f;
    #pragma unroll
    for (int j=0;j<=D;j++)
        s += ws[i*(D+1)+j] * buf[(long long)os[i*(D+1)+j]*NC + c];
    float nrm = (D==DBIL) ? G.normB[i] : G.normS[i];
    float val = wgt * s / nrm;
    if (ACC) G.msg[tid] += val; else G.msg[tid] = val;
}

template<int D>
__global__ void sliceNormK(float alpha, int p){
    int i = blockIdx.x*blockDim.x + threadIdx.x;
    if (i >= NPIX) return;
    const float* nb = p ? G.nbuf1 : G.nbuf0;
    const int*   os = OS<D>(); const float* ws = WSp<D>();
    float s = 0.f;
    #pragma unroll
    for (int j=0;j<=D;j++) s += ws[i*(D+1)+j] * nb[os[i*(D+1)+j]];
    float* nrm = (D==DBIL) ? G.normB : G.normS;
    nrm[i] = alpha * s + 1e-20f;
}

template<bool USE_MSG>
__global__ void softmaxK(const float* __restrict__ U, float* extOut){
    int i = blockIdx.x*blockDim.x + threadIdx.x;
    if (i >= NPIX) return;
    float t[NC];
    float mx = -3.4e38f;
    #pragma unroll
    for (int c=0;c<NC;c++){
        float l = -U[i*NC+c];
        if (USE_MSG) l += G.msg[i*NC+c];
        t[c] = l;
        mx = fmaxf(mx, l);
    }
    float sum = 0.f;
    #pragma unroll
    for (int c=0;c<NC;c++){ float e = expf(t[c]-mx); t[c]=e; sum += e; }
    float inv = 1.0f / sum;
    #pragma unroll
    for (int c=0;c<NC;c++){
        float q = t[c]*inv;
        G.Q[i*NC+c] = q;
        if (extOut) extOut[i*NC+c] = q;
    }
}

// ---------------- host ------------------------------------------------------
static inline unsigned int gridFor(long long n, int B){ return (unsigned int)((n + B - 1) / B); }

extern "C" void kernel_launch(void* const* d_in, const int* in_sizes, int n_in,
                              void* d_out, int out_size){
    const float* unary = nullptr;
    const float* image = nullptr;
    for (int k=0;k<n_in;k++){
        if      (in_sizes[k] == NPIX*NC) unary = (const float*)d_in[k];
        else if (in_sizes[k] == NPIX*3)  image = (const float*)d_in[k];
    }
    if (!unary || !image) return;
    float* out = (float*)d_out;
    const int B = 256;

    const float ALPHA_B = 32.0f/33.0f;   // 1/(1+2^-(d1-1)), d1=6
    const float ALPHA_S = 0.8f;          // d1=3
    const float WB = 10.0f, WSPA = 3.0f;

    // ---- build bilateral lattice ----
    initHashK<DBIL><<<gridFor(HBSZ,B), B>>>();
    buildK<DBIL><<<gridFor(NPIX,B), B>>>(image);
    assignK<DBIL><<<gridFor(HBSZ,B), B>>>();
    osK<DBIL><<<gridFor(NPIX*(DBIL+1),B), B>>>();
    neighK<DBIL><<<gridFor(MBIL,B), B>>>();
    // ---- build spatial lattice ----
    initHashK<DSP><<<gridFor(HSSZ,B), B>>>();
    buildK<DSP><<<gridFor(NPIX,B), B>>>(image);
    assignK<DSP><<<gridFor(HSSZ,B), B>>>();
    osK<DSP><<<gridFor(NPIX*(DSP+1),B), B>>>();
    neighK<DSP><<<gridFor(MSP,B), B>>>();

    // ---- norms (filter of ones) ----
    zeroNK<DBIL><<<gridFor(MBIL,B), B>>>();
    splatNK<DBIL><<<gridFor(NPIX,B), B>>>();
    for (int j=0;j<DBIL+1;j++) blurK<DBIL,1><<<gridFor(MBIL,B), B>>>(j, j&1);
    sliceNormK<DBIL><<<gridFor(NPIX,B), B>>>(ALPHA_B, (DBIL+1)&1);   // 6 passes -> parity 0
    zeroNK<DSP><<<gridFor(MSP,B), B>>>();
    splatNK<DSP><<<gridFor(NPIX,B), B>>>();
    for (int j=0;j<DSP+1;j++) blurK<DSP,1><<<gridFor(MSP,B), B>>>(j, j&1);
    sliceNormK<DSP><<<gridFor(NPIX,B), B>>>(ALPHA_S, (DSP+1)&1);     // 3 passes -> parity 1

    // ---- Q0 = softmax(-U) ----
    softmaxK<false><<<gridFor(NPIX,B), B>>>(unary, nullptr);

    // ---- 5 mean-field iterations ----
    for (int it=0; it<5; ++it){
        zeroBufK<DBIL><<<gridFor((long long)MBIL*NC,B), B>>>();
        splatK<DBIL><<<gridFor(NPIX*NC,B), B>>>();
        for (int j=0;j<DBIL+1;j++) blurK<DBIL,NC><<<gridFor((long long)MBIL*NC,B), B>>>(j, j&1);
        sliceK<DBIL,false><<<gridFor(NPIX*NC,B), B>>>(WB*ALPHA_B, (DBIL+1)&1);

        zeroBufK<DSP><<<gridFor((long long)MSP*NC,B), B>>>();
        splatK<DSP><<<gridFor(NPIX*NC,B), B>>>();
        for (int j=0;j<DSP+1;j++) blurK<DSP,NC><<<gridFor((long long)MSP*NC,B), B>>>(j, j&1);
        sliceK<DSP,true><<<gridFor(NPIX*NC,B), B>>>(WSPA*ALPHA_S, (DSP+1)&1);

        softmaxK<true><<<gridFor(NPIX,B), B>>>(unary, (it==4) ? out : nullptr);
    }
}

// round 2
// speedup vs baseline: 1.4712x; 1.4712x over previous
#include <cuda_runtime.h>
#include <cstdint>
#include <math.h>

// ----------------------------------------------------------------------------
// DenseCRF mean-field with permutohedral lattice filtering, full GPU pipeline.
// Round 2: padded 24-float rows + float4 blur, last-blur-pass fused into slice,
// slice+slice+softmax fused, both splats fused.
// ----------------------------------------------------------------------------

#define HH 320
#define WW 320
#define NPIX (HH*WW)                 // 102400
#define NC 21
#define NCP 24                       // padded channels (6 float4s)
#define NQ4 6
#define DBIL 5
#define DSP 2
#define MBIL (NPIX*(DBIL+1))         // 614400 worst-case unique lattice pts
#define MSP  (NPIX*(DSP+1))          // 307200
#define HBSZ (1u<<21)
#define HSSZ (1u<<20)
#define EMPTYK 0xFFFFFFFFFFFFFFFFULL

struct Globals {
    unsigned long long hkeyB[HBSZ];
    int                hidxB[HBSZ];
    unsigned long long hkeyS[HSSZ];
    int                hidxS[HSSZ];
    int countB, countS, pad_[2];
    unsigned long long ukeyB[MBIL];
    unsigned long long ukeyS[MSP];
    unsigned long long pkB[NPIX*(DBIL+1)];
    unsigned long long pkS[NPIX*(DSP+1)];
    int   osB[NPIX*(DBIL+1)];
    float wsB[NPIX*(DBIL+1)];
    int   osS[NPIX*(DSP+1)];
    float wsS[NPIX*(DSP+1)];
    int n1B[(DBIL+1)*MBIL];
    int n2B[(DBIL+1)*MBIL];
    int n1S[(DSP+1)*MSP];
    int n2S[(DSP+1)*MSP];
    float4 bufB0[(long long)MBIL*NQ4];
    float4 bufB1[(long long)MBIL*NQ4];
    float4 bufS0[(long long)MSP*NQ4];
    float4 bufS1[(long long)MSP*NQ4];
    float nbuf0[MBIL];
    float nbuf1[MBIL];
    float normB[NPIX];
    float normS[NPIX];
    float4 Q[NPIX*NQ4];
};
__device__ Globals G;

// ---------------- lattice selectors -----------------------------------------
template<int D> __device__ __forceinline__ unsigned long long* HK()   { return (D==DBIL)? G.hkeyB : G.hkeyS; }
template<int D> __device__ __forceinline__ int*                HI()   { return (D==DBIL)? G.hidxB : G.hidxS; }
template<int D> __device__ __forceinline__ int*                CNT()  { return (D==DBIL)? &G.countB : &G.countS; }
template<int D> __device__ __forceinline__ unsigned long long* UK()   { return (D==DBIL)? G.ukeyB : G.ukeyS; }
template<int D> __device__ __forceinline__ unsigned long long* PK()   { return (D==DBIL)? G.pkB : G.pkS; }
template<int D> __device__ __forceinline__ int*                OS()   { return (D==DBIL)? G.osB : G.osS; }
template<int D> __device__ __forceinline__ float*              WSp()  { return (D==DBIL)? G.wsB : G.wsS; }
template<int D> __device__ __forceinline__ int*                N1()   { return (D==DBIL)? G.n1B : G.n1S; }
template<int D> __device__ __forceinline__ int*                N2()   { return (D==DBIL)? G.n2B : G.n2S; }
template<int D> __device__ __forceinline__ float4*             BUFP(int p){
    if (D==DBIL) return p ? G.bufB1 : G.bufB0;
    else         return p ? G.bufS1 : G.bufS0;
}
template<int D> __host__ __device__ constexpr unsigned int HMSK(){ return (D==DBIL)? (HBSZ-1u) : (HSSZ-1u); }
template<int D> __host__ __device__ constexpr unsigned int HSZ (){ return (D==DBIL)? HBSZ : HSSZ; }
template<int D> __host__ __device__ constexpr int          MMAX(){ return (D==DBIL)? MBIL : MSP; }

// ---------------- hash ------------------------------------------------------
__device__ __forceinline__ unsigned int hmix(unsigned long long x, unsigned int mask){
    x ^= x >> 33; x *= 0xff51afd7ed558ccdULL;
    x ^= x >> 33; x *= 0xc4ceb9fe1a85ec53ULL;
    x ^= x >> 33;
    return (unsigned int)x & mask;
}
__device__ __forceinline__ void hinsert(unsigned long long* hk, unsigned int mask, unsigned long long key){
    unsigned int s = hmix(key, mask);
    while (true){
        unsigned long long prev = atomicCAS(&hk[s], EMPTYK, key);
        if (prev == EMPTYK || prev == key) return;
        s = (s+1) & mask;
    }
}
__device__ __forceinline__ int hlookup(const unsigned long long* hk, const int* hi,
                                       unsigned int mask, unsigned long long key){
    unsigned int s = hmix(key, mask);
    while (true){
        unsigned long long k = hk[s];
        if (k == key)    return hi[s];
        if (k == EMPTYK) return -1;
        s = (s+1) & mask;
    }
}

// ---------------- lattice build ---------------------------------------------
template<int D>
__global__ void initHashK(){
    unsigned int s = blockIdx.x*blockDim.x + threadIdx.x;
    if (s < HSZ<D>()) HK<D>()[s] = EMPTYK;
    if (s == 0) *CNT<D>() = 0;
}

template<int D>
__global__ void buildK(const float* __restrict__ image){
    int i = blockIdx.x*blockDim.x + threadIdx.x;
    if (i >= NPIX) return;
    float f[D];
    float x = (float)(i % WW), y = (float)(i / WW);
    if constexpr (D == DBIL){
        f[0] = x / 80.0f;  f[1] = y / 80.0f;
        f[2] = image[i*3+0] / 13.0f;
        f[3] = image[i*3+1] / 13.0f;
        f[4] = image[i*3+2] / 13.0f;
    } else {
        f[0] = x / 3.0f;   f[1] = y / 3.0f;
    }
    float cf[D];
    #pragma unroll
    for (int k=0;k<D;k++){
        double sc = sqrt(2.0/3.0) * (double)(D+1) / sqrt((double)((k+1)*(k+2)));
        cf[k] = f[k] * (float)sc;
    }
    float suf[D];
    { float s=0.f; for (int k=D-1;k>=0;k--){ s += cf[k]; suf[k]=s; } }
    float el[D+1];
    el[0] = suf[0];
    #pragma unroll
    for (int k=1;k<=D;k++){
        float t = (k<D) ? suf[k] : 0.0f;
        el[k] = t - (float)k * cf[k-1];
    }
    const float down = 1.0f/(float)(D+1);
    float rem0[D+1]; int rank[D+1]; int ssum=0;
    #pragma unroll
    for (int k=0;k<=D;k++){
        float rd = rintf(el[k]*down);
        rem0[k] = rd * (float)(D+1);
        ssum += (int)rd;
    }
    float diff[D+1];
    #pragma unroll
    for (int k=0;k<=D;k++) diff[k] = el[k] - rem0[k];
    #pragma unroll
    for (int a=0;a<=D;a++){
        int r = 0;
        #pragma unroll
        for (int b=0;b<=D;b++)
            if (diff[b] > diff[a] || (diff[b] == diff[a] && b < a)) r++;
        rank[a] = r + ssum;
    }
    #pragma unroll
    for (int k=0;k<=D;k++){
        if (rank[k] < 0)      { rank[k] += D+1; rem0[k] += (float)(D+1); }
        else if (rank[k] > D) { rank[k] -= D+1; rem0[k] -= (float)(D+1); }
    }
    float bb[D+2];
    #pragma unroll
    for (int k=0;k<D+2;k++) bb[k]=0.f;
    #pragma unroll
    for (int k=0;k<=D;k++){
        float v = (el[k]-rem0[k]) * down;
        bb[D   - rank[k]] += v;
        bb[D+1 - rank[k]] -= v;
    }
    bb[0] += 1.0f + bb[D+1];
    int key0[D];
    #pragma unroll
    for (int k=0;k<D;k++) key0[k] = (int)lrintf(rem0[k]);
    unsigned long long* hk = HK<D>();
    const unsigned int mask = HMSK<D>();
    #pragma unroll
    for (int r=0;r<=D;r++){
        unsigned long long pk = 0;
        #pragma unroll
        for (int k=0;k<D;k++){
            int canon = (rank[k] < D+1-r) ? r : r-(D+1);
            pk |= ((unsigned long long)(unsigned int)(key0[k]+canon+2048) & 0xFFFULL) << (12*k);
        }
        WSp<D>()[i*(D+1)+r] = bb[r];
        PK<D>()[i*(D+1)+r]  = pk;
        hinsert(hk, mask, pk);
    }
}

template<int D>
__global__ void assignK(){
    unsigned int s = blockIdx.x*blockDim.x + threadIdx.x;
    if (s >= HSZ<D>()) return;
    unsigned long long k = HK<D>()[s];
    if (k != EMPTYK){
        int idx = atomicAdd(CNT<D>(), 1);
        HI<D>()[s] = idx;
        UK<D>()[idx] = k;
    }
}

template<int D>
__global__ void osK(){
    int tid = blockIdx.x*blockDim.x + threadIdx.x;
    if (tid >= NPIX*(D+1)) return;
    OS<D>()[tid] = hlookup(HK<D>(), HI<D>(), HMSK<D>(), PK<D>()[tid]);
}

template<int D>
__global__ void neighK(){
    int m = blockIdx.x*blockDim.x + threadIdx.x;
    if (m >= *CNT<D>()) return;
    unsigned long long k = UK<D>()[m];
    int c[D];
    #pragma unroll
    for (int t=0;t<D;t++) c[t] = (int)((k >> (12*t)) & 0xFFF) - 2048;
    unsigned long long* hk = HK<D>(); int* hi = HI<D>();
    const unsigned int mask = HMSK<D>();
    #pragma unroll
    for (int j=0;j<=D;j++){
        unsigned long long p1=0, p2=0;
        #pragma unroll
        for (int t=0;t<D;t++){
            int a1 = c[t]-1 + ((t==j)?(D+1):0);
            int a2 = c[t]+1 - ((t==j)?(D+1):0);
            p1 |= ((unsigned long long)(unsigned int)(a1+2048) & 0xFFFULL) << (12*t);
            p2 |= ((unsigned long long)(unsigned int)(a2+2048) & 0xFFFULL) << (12*t);
        }
        N1<D>()[j*MMAX<D>()+m] = hlookup(hk, hi, mask, p1);
        N2<D>()[j*MMAX<D>()+m] = hlookup(hk, hi, mask, p2);
    }
}

// ---------------- normalization filter (C=1, scalar) ------------------------
template<int D>
__global__ void zeroNK(){
    int tid = blockIdx.x*blockDim.x + threadIdx.x;
    if (tid < *CNT<D>()) G.nbuf0[tid] = 0.f;
}
template<int D>
__global__ void splatNK(){
    int i = blockIdx.x*blockDim.x + threadIdx.x;
    if (i >= NPIX) return;
    const int* os = OS<D>(); const float* ws = WSp<D>();
    #pragma unroll
    for (int j=0;j<=D;j++)
        atomicAdd(&G.nbuf0[os[i*(D+1)+j]], ws[i*(D+1)+j]);
}
template<int D>
__global__ void blurNK(int j, int p){
    int m = blockIdx.x*blockDim.x + threadIdx.x;
    if (m >= *CNT<D>()) return;
    const float* in = p ? G.nbuf1 : G.nbuf0;
    float*      out = p ? G.nbuf0 : G.nbuf1;
    int a = N1<D>()[j*MMAX<D>()+m];
    int b = N2<D>()[j*MMAX<D>()+m];
    float va = (a >= 0) ? in[a] : 0.f;
    float vb = (b >= 0) ? in[b] : 0.f;
    out[m] = in[m] + 0.5f*(va + vb);
}
template<int D>
__global__ void sliceNormK(float alpha, int p){
    int i = blockIdx.x*blockDim.x + threadIdx.x;
    if (i >= NPIX) return;
    const float* nb = p ? G.nbuf1 : G.nbuf0;
    const int*   os = OS<D>(); const float* ws = WSp<D>();
    float s = 0.f;
    #pragma unroll
    for (int j=0;j<=D;j++) s += ws[i*(D+1)+j] * nb[os[i*(D+1)+j]];
    float* nrm = (D==DBIL) ? G.normB : G.normS;
    nrm[i] = alpha * s + 1e-20f;
}

// ---------------- mean-field loop kernels -----------------------------------
template<int D>
__global__ void zeroBufK(){
    long long tid = (long long)blockIdx.x*blockDim.x + threadIdx.x;
    long long n = (long long)(*CNT<D>()) * NQ4;
    if (tid < n) BUFP<D>(0)[tid] = make_float4(0.f,0.f,0.f,0.f);
}

// fused splat into both lattices; thread per (pixel, float4-quarter)
__global__ void splatFusedK(){
    int tid = blockIdx.x*blockDim.x + threadIdx.x;
    if (tid >= NPIX*NQ4) return;
    int i = tid / NQ4, q = tid % NQ4;
    float4 qv = G.Q[tid];
    int base = q*4;
    #pragma unroll
    for (int j=0;j<=DBIL;j++){
        int m   = G.osB[i*(DBIL+1)+j];
        float w = G.wsB[i*(DBIL+1)+j];
        float* row = (float*)&G.bufB0[(long long)m*NQ4 + q];
        atomicAdd(row+0, w*qv.x);
        atomicAdd(row+1, w*qv.y);
        atomicAdd(row+2, w*qv.z);
        if (base+3 < NC) atomicAdd(row+3, w*qv.w);
    }
    #pragma unroll
    for (int j=0;j<=DSP;j++){
        int m   = G.osS[i*(DSP+1)+j];
        float w = G.wsS[i*(DSP+1)+j];
        float* row = (float*)&G.bufS0[(long long)m*NQ4 + q];
        atomicAdd(row+0, w*qv.x);
        atomicAdd(row+1, w*qv.y);
        atomicAdd(row+2, w*qv.z);
        if (base+3 < NC) atomicAdd(row+3, w*qv.w);
    }
}

__device__ __forceinline__ float4 f4fma(float4 a, float s, float4 b){
    return make_float4(fmaf(a.x,s,b.x), fmaf(a.y,s,b.y), fmaf(a.z,s,b.z), fmaf(a.w,s,b.w));
}
__device__ __forceinline__ float4 f4add(float4 a, float4 b){
    return make_float4(a.x+b.x, a.y+b.y, a.z+b.z, a.w+b.w);
}

// one blur pass, float4 per thread
template<int D>
__global__ void blur4K(int j, int p){
    long long tid = (long long)blockIdx.x*blockDim.x + threadIdx.x;
    int M = *CNT<D>();
    int m = (int)(tid / NQ4), q = (int)(tid % NQ4);
    if (m >= M) return;
    const float4* __restrict__ in  = BUFP<D>(p);
    float4*       __restrict__ out = BUFP<D>(1-p);
    int a = N1<D>()[j*MMAX<D>()+m];
    int b = N2<D>()[j*MMAX<D>()+m];
    float4 self = in[(long long)m*NQ4+q];
    float4 acc = make_float4(0.f,0.f,0.f,0.f);
    if (a >= 0) acc = in[(long long)a*NQ4+q];
    if (b >= 0) acc = f4add(acc, in[(long long)b*NQ4+q]);
    out[(long long)m*NQ4+q] = f4fma(acc, 0.5f, self);
}

// fused: (last bilateral blur pass j=5) + sliceB + (last spatial pass j=2) +
// sliceS + softmax.  One thread per pixel.
__global__ void fusedSliceSoftmaxK(const float* __restrict__ U,
                                   float* __restrict__ out, int writeOut,
                                   float fBmul, float fSmul){
    int i = blockIdx.x*blockDim.x + threadIdx.x;
    if (i >= NPIX) return;

    int   osb[DBIL+1]; float wsb[DBIL+1];
    int   a1b[DBIL+1], a2b[DBIL+1];
    #pragma unroll
    for (int j=0;j<=DBIL;j++){
        osb[j] = G.osB[i*(DBIL+1)+j];
        wsb[j] = G.wsB[i*(DBIL+1)+j];
        a1b[j] = G.n1B[DBIL*MBIL + osb[j]];
        a2b[j] = G.n2B[DBIL*MBIL + osb[j]];
    }
    int   oss[DSP+1]; float wss[DSP+1];
    int   a1s[DSP+1], a2s[DSP+1];
    #pragma unroll
    for (int j=0;j<=DSP;j++){
        oss[j] = G.osS[i*(DSP+1)+j];
        wss[j] = G.wsS[i*(DSP+1)+j];
        a1s[j] = G.n1S[DSP*MSP + oss[j]];
        a2s[j] = G.n2S[DSP*MSP + oss[j]];
    }
    float fB = fBmul / G.normB[i];
    float fS = fSmul / G.normS[i];

    const float4* __restrict__ bB = G.bufB1;  // after 5 passes, cur = bufB1
    const float4* __restrict__ bS = G.bufS0;  // after 2 passes, cur = bufS0

    float lg[NCP];
    float mx = -3.4e38f;
    #pragma unroll
    for (int q=0;q<NQ4;q++){
        float4 sB = make_float4(0.f,0.f,0.f,0.f);
        #pragma unroll
        for (int j=0;j<=DBIL;j++){
            float4 v = bB[(long long)osb[j]*NQ4+q];
            float4 nb = make_float4(0.f,0.f,0.f,0.f);
            if (a1b[j] >= 0) nb = bB[(long long)a1b[j]*NQ4+q];
            if (a2b[j] >= 0) nb = f4add(nb, bB[(long long)a2b[j]*NQ4+q]);
            v = f4fma(nb, 0.5f, v);
            sB = f4fma(v, wsb[j], sB);
        }
        float4 sS = make_float4(0.f,0.f,0.f,0.f);
        #pragma unroll
        for (int j=0;j<=DSP;j++){
            float4 v = bS[(long long)oss[j]*NQ4+q];
            float4 nb = make_float4(0.f,0.f,0.f,0.f);
            if (a1s[j] >= 0) nb = bS[(long long)a1s[j]*NQ4+q];
            if (a2s[j] >= 0) nb = f4add(nb, bS[(long long)a2s[j]*NQ4+q]);
            v = f4fma(nb, 0.5f, v);
            sS = f4fma(v, wss[j], sS);
        }
        #pragma unroll
        for (int k=0;k<4;k++){
            int ch = q*4+k;
            float m4 = (k==0)?(fB*sB.x+fS*sS.x):(k==1)?(fB*sB.y+fS*sS.y)
                     : (k==2)?(fB*sB.z+fS*sS.z):(fB*sB.w+fS*sS.w);
            float l = (ch < NC) ? (-U[i*NC+ch] + m4) : -3.4e38f;
            lg[q*4+k] = l;
            mx = fmaxf(mx, l);
        }
    }
    float sum = 0.f;
    #pragma unroll
    for (int c=0;c<NCP;c++){
        float e = (lg[c] > -1e37f) ? expf(lg[c]-mx) : 0.f;
        lg[c] = e; sum += e;
    }
    float inv = 1.0f / sum;
    #pragma unroll
    for (int q=0;q<NQ4;q++){
        float4 qv = make_float4(lg[q*4+0]*inv, lg[q*4+1]*inv, lg[q*4+2]*inv, lg[q*4+3]*inv);
        G.Q[i*NQ4+q] = qv;
        if (writeOut){
            int base = q*4;
            float* o = out + (long long)i*NC;
            o[base+0] = qv.x;
            if (base+1 < NC) o[base+1] = qv.y;
            if (base+2 < NC) o[base+2] = qv.z;
            if (base+3 < NC) o[base+3] = qv.w;
        }
    }
}

__global__ void softmax0K(const float* __restrict__ U){
    int i = blockIdx.x*blockDim.x + threadIdx.x;
    if (i >= NPIX) return;
    float t[NC];
    float mx = -3.4e38f;
    #pragma unroll
    for (int c=0;c<NC;c++){
        float l = -U[i*NC+c];
        t[c] = l; mx = fmaxf(mx, l);
    }
    float sum = 0.f;
    #pragma unroll
    for (int c=0;c<NC;c++){ float e = expf(t[c]-mx); t[c]=e; sum += e; }
    float inv = 1.0f / sum;
    float* q = (float*)&G.Q[i*NQ4];
    #pragma unroll
    for (int c=0;c<NC;c++) q[c] = t[c]*inv;
    #pragma unroll
    for (int c=NC;c<NCP;c++) q[c] = 0.f;
}

// ---------------- host ------------------------------------------------------
static inline unsigned int gridFor(long long n, int B){ return (unsigned int)((n + B - 1) / B); }

extern "C" void kernel_launch(void* const* d_in, const int* in_sizes, int n_in,
                              void* d_out, int out_size){
    const float* unary = nullptr;
    const float* image = nullptr;
    for (int k=0;k<n_in;k++){
        if      (in_sizes[k] == NPIX*NC) unary = (const float*)d_in[k];
        else if (in_sizes[k] == NPIX*3)  image = (const float*)d_in[k];
    }
    if (!unary || !image) return;
    float* out = (float*)d_out;
    const int B = 256;

    const float ALPHA_B = 32.0f/33.0f;   // 1/(1+2^-(d1-1)), d1=6
    const float ALPHA_S = 0.8f;          // d1=3
    const float WB = 10.0f, WSPA = 3.0f;

    // ---- build lattices ----
    initHashK<DBIL><<<gridFor(HBSZ,B), B>>>();
    buildK<DBIL><<<gridFor(NPIX,B), B>>>(image);
    assignK<DBIL><<<gridFor(HBSZ,B), B>>>();
    osK<DBIL><<<gridFor(NPIX*(DBIL+1),B), B>>>();
    neighK<DBIL><<<gridFor(MBIL,B), B>>>();

    initHashK<DSP><<<gridFor(HSSZ,B), B>>>();
    buildK<DSP><<<gridFor(NPIX,B), B>>>(image);
    assignK<DSP><<<gridFor(HSSZ,B), B>>>();
    osK<DSP><<<gridFor(NPIX*(DSP+1),B), B>>>();
    neighK<DSP><<<gridFor(MSP,B), B>>>();

    // ---- norms (filter of ones, scalar path) ----
    zeroNK<DBIL><<<gridFor(MBIL,B), B>>>();
    splatNK<DBIL><<<gridFor(NPIX,B), B>>>();
    for (int j=0;j<DBIL+1;j++) blurNK<DBIL><<<gridFor(MBIL,B), B>>>(j, j&1);
    sliceNormK<DBIL><<<gridFor(NPIX,B), B>>>(ALPHA_B, (DBIL+1)&1);
    zeroNK<DSP><<<gridFor(MSP,B), B>>>();
    splatNK<DSP><<<gridFor(NPIX,B), B>>>();
    for (int j=0;j<DSP+1;j++) blurNK<DSP><<<gridFor(MSP,B), B>>>(j, j&1);
    sliceNormK<DSP><<<gridFor(NPIX,B), B>>>(ALPHA_S, (DSP+1)&1);

    // ---- Q0 = softmax(-U) ----
    softmax0K<<<gridFor(NPIX,B), B>>>(unary);

    // ---- 5 mean-field iterations ----
    for (int it=0; it<5; ++it){
        zeroBufK<DBIL><<<gridFor((long long)MBIL*NQ4,B), B>>>();
        zeroBufK<DSP><<<gridFor((long long)MSP*NQ4,B), B>>>();
        splatFusedK<<<gridFor(NPIX*NQ4,B), B>>>();

        // bilateral: 5 passes (j=0..4), 6th (j=5) fused into slice
        for (int j=0;j<DBIL;j++)
            blur4K<DBIL><<<gridFor((long long)MBIL*NQ4,B), B>>>(j, j&1);
        // spatial: 2 passes (j=0..1), 3rd (j=2) fused into slice
        for (int j=0;j<DSP;j++)
            blur4K<DSP><<<gridFor((long long)MSP*NQ4,B), B>>>(j, j&1);

        fusedSliceSoftmaxK<<<gridFor(NPIX,B), B>>>(
            unary, out, (it==4) ? 1 : 0,
            WB*ALPHA_B, WSPA*ALPHA_S);
    }
}

// round 3
// speedup vs baseline: 1.6138x; 1.0969x over previous
#include <cuda_runtime.h>
#include <cstdint>
#include <math.h>

// ----------------------------------------------------------------------------
// DenseCRF mean-field, permutohedral lattice. Round 3:
//  - CSR gather splat (no zeroing, no atomics in the hot loop)
//  - bilateral blur buffers split into 2 channel segments (48B rows) so the
//    per-segment ping-pong (59MB) stays L2-resident
//  - fused last-blur+slice+slice+softmax kernel (as round 2)
// ----------------------------------------------------------------------------

#define HH 320
#define WW 320
#define NPIX (HH*WW)                 // 102400
#define NC 21
#define NCP 24
#define NQ4 6                        // float4s per pixel Q row
#define SEGW 3                       // float4s per bilateral segment row
#define DBIL 5
#define DSP 2
#define MBIL (NPIX*(DBIL+1))         // 614400
#define MSP  (NPIX*(DSP+1))          // 307200
#define HBSZ (1u<<21)
#define HSSZ (1u<<20)
#define EMPTYK 0xFFFFFFFFFFFFFFFFULL

struct Globals {
    unsigned long long hkeyB[HBSZ];
    int                hidxB[HBSZ];
    unsigned long long hkeyS[HSSZ];
    int                hidxS[HSSZ];
    int countB, countS, pad_[2];
    unsigned long long ukeyB[MBIL];
    unsigned long long ukeyS[MSP];
    unsigned long long pkB[NPIX*(DBIL+1)];
    unsigned long long pkS[NPIX*(DSP+1)];
    int   osB[NPIX*(DBIL+1)];
    float wsB[NPIX*(DBIL+1)];
    int   osS[NPIX*(DSP+1)];
    float wsS[NPIX*(DSP+1)];
    int n1B[(DBIL+1)*MBIL];
    int n2B[(DBIL+1)*MBIL];
    int n1S[(DSP+1)*MSP];
    int n2S[(DSP+1)*MSP];
    // CSR (pixel entries per lattice row)
    int   cntB[MBIL], startB[MBIL], fillB[MBIL];
    int   cntS[MSP],  startS[MSP],  fillS[MSP];
    int   bsumB[4096], bsumS[4096];
    int   entryPixB[NPIX*(DBIL+1)];
    float entryWB [NPIX*(DBIL+1)];
    int   entryPixS[NPIX*(DSP+1)];
    float entryWS [NPIX*(DSP+1)];
    // blur buffers: bilateral segmented [2][MBIL][3], spatial [MSP][6]
    float4 bufB0[2ll*MBIL*SEGW];
    float4 bufB1[2ll*MBIL*SEGW];
    float4 bufS0[(long long)MSP*NQ4];
    float4 bufS1[(long long)MSP*NQ4];
    float nbuf0[MBIL];
    float nbuf1[MBIL];
    float normB[NPIX];
    float normS[NPIX];
    float4 Q[NPIX*NQ4];
};
__device__ Globals G;

// ---------------- selectors --------------------------------------------------
template<int D> __device__ __forceinline__ unsigned long long* HK()   { return (D==DBIL)? G.hkeyB : G.hkeyS; }
template<int D> __device__ __forceinline__ int*                HI()   { return (D==DBIL)? G.hidxB : G.hidxS; }
template<int D> __device__ __forceinline__ int*                CNTp() { return (D==DBIL)? &G.countB : &G.countS; }
template<int D> __device__ __forceinline__ unsigned long long* UK()   { return (D==DBIL)? G.ukeyB : G.ukeyS; }
template<int D> __device__ __forceinline__ unsigned long long* PK()   { return (D==DBIL)? G.pkB : G.pkS; }
template<int D> __device__ __forceinline__ int*                OS()   { return (D==DBIL)? G.osB : G.osS; }
template<int D> __device__ __forceinline__ float*              WSp()  { return (D==DBIL)? G.wsB : G.wsS; }
template<int D> __device__ __forceinline__ int*                N1()   { return (D==DBIL)? G.n1B : G.n1S; }
template<int D> __device__ __forceinline__ int*                N2()   { return (D==DBIL)? G.n2B : G.n2S; }
template<int D> __device__ __forceinline__ int*                RCNT() { return (D==DBIL)? G.cntB : G.cntS; }
template<int D> __device__ __forceinline__ int*                RST()  { return (D==DBIL)? G.startB : G.startS; }
template<int D> __device__ __forceinline__ int*                RFIL() { return (D==DBIL)? G.fillB : G.fillS; }
template<int D> __device__ __forceinline__ int*                BSUM() { return (D==DBIL)? G.bsumB : G.bsumS; }
template<int D> __device__ __forceinline__ int*                EPIX() { return (D==DBIL)? G.entryPixB : G.entryPixS; }
template<int D> __device__ __forceinline__ float*              EW()   { return (D==DBIL)? G.entryWB : G.entryWS; }
template<int D> __host__ __device__ constexpr unsigned int HMSK(){ return (D==DBIL)? (HBSZ-1u) : (HSSZ-1u); }
template<int D> __host__ __device__ constexpr unsigned int HSZ (){ return (D==DBIL)? HBSZ : HSSZ; }
template<int D> __host__ __device__ constexpr int          MMAX(){ return (D==DBIL)? MBIL : MSP; }

// ---------------- hash -------------------------------------------------------
__device__ __forceinline__ unsigned int hmix(unsigned long long x, unsigned int mask){
    x ^= x >> 33; x *= 0xff51afd7ed558ccdULL;
    x ^= x >> 33; x *= 0xc4ceb9fe1a85ec53ULL;
    x ^= x >> 33;
    return (unsigned int)x & mask;
}
__device__ __forceinline__ void hinsert(unsigned long long* hk, unsigned int mask, unsigned long long key){
    unsigned int s = hmix(key, mask);
    while (true){
        unsigned long long prev = atomicCAS(&hk[s], EMPTYK, key);
        if (prev == EMPTYK || prev == key) return;
        s = (s+1) & mask;
    }
}
__device__ __forceinline__ int hlookup(const unsigned long long* hk, const int* hi,
                                       unsigned int mask, unsigned long long key){
    unsigned int s = hmix(key, mask);
    while (true){
        unsigned long long k = hk[s];
        if (k == key)    return hi[s];
        if (k == EMPTYK) return -1;
        s = (s+1) & mask;
    }
}

// ---------------- lattice build ----------------------------------------------
template<int D>
__global__ void initHashK(){
    unsigned int s = blockIdx.x*blockDim.x + threadIdx.x;
    if (s < HSZ<D>()) HK<D>()[s] = EMPTYK;
    if (s == 0) *CNTp<D>() = 0;
}

template<int D>
__global__ void buildK(const float* __restrict__ image){
    int i = blockIdx.x*blockDim.x + threadIdx.x;
    if (i >= NPIX) return;
    float f[D];
    float x = (float)(i % WW), y = (float)(i / WW);
    if constexpr (D == DBIL){
        f[0] = x / 80.0f;  f[1] = y / 80.0f;
        f[2] = image[i*3+0] / 13.0f;
        f[3] = image[i*3+1] / 13.0f;
        f[4] = image[i*3+2] / 13.0f;
    } else {
        f[0] = x / 3.0f;   f[1] = y / 3.0f;
    }
    float cf[D];
    #pragma unroll
    for (int k=0;k<D;k++){
        double sc = sqrt(2.0/3.0) * (double)(D+1) / sqrt((double)((k+1)*(k+2)));
        cf[k] = f[k] * (float)sc;
    }
    float suf[D];
    { float s=0.f; for (int k=D-1;k>=0;k--){ s += cf[k]; suf[k]=s; } }
    float el[D+1];
    el[0] = suf[0];
    #pragma unroll
    for (int k=1;k<=D;k++){
        float t = (k<D) ? suf[k] : 0.0f;
        el[k] = t - (float)k * cf[k-1];
    }
    const float down = 1.0f/(float)(D+1);
    float rem0[D+1]; int rank[D+1]; int ssum=0;
    #pragma unroll
    for (int k=0;k<=D;k++){
        float rd = rintf(el[k]*down);
        rem0[k] = rd * (float)(D+1);
        ssum += (int)rd;
    }
    float diff[D+1];
    #pragma unroll
    for (int k=0;k<=D;k++) diff[k] = el[k] - rem0[k];
    #pragma unroll
    for (int a=0;a<=D;a++){
        int r = 0;
        #pragma unroll
        for (int b=0;b<=D;b++)
            if (diff[b] > diff[a] || (diff[b] == diff[a] && b < a)) r++;
        rank[a] = r + ssum;
    }
    #pragma unroll
    for (int k=0;k<=D;k++){
        if (rank[k] < 0)      { rank[k] += D+1; rem0[k] += (float)(D+1); }
        else if (rank[k] > D) { rank[k] -= D+1; rem0[k] -= (float)(D+1); }
    }
    float bb[D+2];
    #pragma unroll
    for (int k=0;k<D+2;k++) bb[k]=0.f;
    #pragma unroll
    for (int k=0;k<=D;k++){
        float v = (el[k]-rem0[k]) * down;
        bb[D   - rank[k]] += v;
        bb[D+1 - rank[k]] -= v;
    }
    bb[0] += 1.0f + bb[D+1];
    int key0[D];
    #pragma unroll
    for (int k=0;k<D;k++) key0[k] = (int)lrintf(rem0[k]);
    unsigned long long* hk = HK<D>();
    const unsigned int mask = HMSK<D>();
    #pragma unroll
    for (int r=0;r<=D;r++){
        unsigned long long pk = 0;
        #pragma unroll
        for (int k=0;k<D;k++){
            int canon = (rank[k] < D+1-r) ? r : r-(D+1);
            pk |= ((unsigned long long)(unsigned int)(key0[k]+canon+2048) & 0xFFFULL) << (12*k);
        }
        WSp<D>()[i*(D+1)+r] = bb[r];
        PK<D>()[i*(D+1)+r]  = pk;
        hinsert(hk, mask, pk);
    }
}

template<int D>
__global__ void assignK(){
    unsigned int s = blockIdx.x*blockDim.x + threadIdx.x;
    if (s >= HSZ<D>()) return;
    unsigned long long k = HK<D>()[s];
    if (k != EMPTYK){
        int idx = atomicAdd(CNTp<D>(), 1);
        HI<D>()[s] = idx;
        UK<D>()[idx] = k;
    }
}

template<int D>
__global__ void osK(){
    int tid = blockIdx.x*blockDim.x + threadIdx.x;
    if (tid >= NPIX*(D+1)) return;
    OS<D>()[tid] = hlookup(HK<D>(), HI<D>(), HMSK<D>(), PK<D>()[tid]);
}

template<int D>
__global__ void neighK(){
    int m = blockIdx.x*blockDim.x + threadIdx.x;
    if (m >= *CNTp<D>()) return;
    unsigned long long k = UK<D>()[m];
    int c[D];
    #pragma unroll
    for (int t=0;t<D;t++) c[t] = (int)((k >> (12*t)) & 0xFFF) - 2048;
    unsigned long long* hk = HK<D>(); int* hi = HI<D>();
    const unsigned int mask = HMSK<D>();
    #pragma unroll
    for (int j=0;j<=D;j++){
        unsigned long long p1=0, p2=0;
        #pragma unroll
        for (int t=0;t<D;t++){
            int a1 = c[t]-1 + ((t==j)?(D+1):0);
            int a2 = c[t]+1 - ((t==j)?(D+1):0);
            p1 |= ((unsigned long long)(unsigned int)(a1+2048) & 0xFFFULL) << (12*t);
            p2 |= ((unsigned long long)(unsigned int)(a2+2048) & 0xFFFULL) << (12*t);
        }
        N1<D>()[j*MMAX<D>()+m] = hlookup(hk, hi, mask, p1);
        N2<D>()[j*MMAX<D>()+m] = hlookup(hk, hi, mask, p2);
    }
}

// ---------------- CSR build --------------------------------------------------
template<int D>
__global__ void zeroCntK(){
    int m = blockIdx.x*blockDim.x + threadIdx.x;
    if (m < MMAX<D>()) RCNT<D>()[m] = 0;
}
template<int D>
__global__ void countRowsK(){
    int t = blockIdx.x*blockDim.x + threadIdx.x;
    if (t >= NPIX*(D+1)) return;
    atomicAdd(&RCNT<D>()[OS<D>()[t]], 1);
}
template<int D>
__global__ void scanAK(){
    __shared__ int sh[256];
    int t = threadIdx.x;
    int g = blockIdx.x*256 + t;
    int v = (g < MMAX<D>()) ? RCNT<D>()[g] : 0;
    sh[t] = v; __syncthreads();
    #pragma unroll
    for (int o=1;o<256;o<<=1){
        int x = (t>=o) ? sh[t-o] : 0;
        __syncthreads();
        sh[t] += x;
        __syncthreads();
    }
    if (g < MMAX<D>()) RST<D>()[g] = sh[t] - v;   // exclusive within block
    if (t == 255) BSUM<D>()[blockIdx.x] = sh[255];
}
template<int D>
__global__ void scanBK(){
    __shared__ int sh[1024];
    const int nb = MMAX<D>() / 256;
    int t = threadIdx.x;
    int carry = 0;
    for (int base=0; base<nb; base+=1024){
        int v = (base+t < nb) ? BSUM<D>()[base+t] : 0;
        sh[t] = v; __syncthreads();
        for (int o=1;o<1024;o<<=1){
            int x = (t>=o) ? sh[t-o] : 0;
            __syncthreads();
            sh[t] += x;
            __syncthreads();
        }
        int tot = sh[1023];
        if (base+t < nb) BSUM<D>()[base+t] = sh[t] - v + carry;
        __syncthreads();
        carry += tot;
    }
}
template<int D>
__global__ void scanCK(){
    int g = blockIdx.x*256 + threadIdx.x;
    if (g >= MMAX<D>()) return;
    int s = RST<D>()[g] + BSUM<D>()[g >> 8];
    RST<D>()[g]  = s;
    RFIL<D>()[g] = s;
}
template<int D>
__global__ void fillK(){
    int t = blockIdx.x*blockDim.x + threadIdx.x;
    if (t >= NPIX*(D+1)) return;
    int m = OS<D>()[t];
    int p = atomicAdd(&RFIL<D>()[m], 1);
    EPIX<D>()[p] = t / (D+1);
    EW<D>()[p]   = WSp<D>()[t];
}

// ---------------- norm filter (scalar, one-time) -----------------------------
template<int D>
__global__ void zeroNK(){
    int tid = blockIdx.x*blockDim.x + threadIdx.x;
    if (tid < *CNTp<D>()) G.nbuf0[tid] = 0.f;
}
template<int D>
__global__ void splatNK(){
    int i = blockIdx.x*blockDim.x + threadIdx.x;
    if (i >= NPIX) return;
    const int* os = OS<D>(); const float* ws = WSp<D>();
    #pragma unroll
    for (int j=0;j<=D;j++)
        atomicAdd(&G.nbuf0[os[i*(D+1)+j]], ws[i*(D+1)+j]);
}
template<int D>
__global__ void blurNK(int j, int p){
    int m = blockIdx.x*blockDim.x + threadIdx.x;
    if (m >= *CNTp<D>()) return;
    const float* in = p ? G.nbuf1 : G.nbuf0;
    float*      out = p ? G.nbuf0 : G.nbuf1;
    int a = N1<D>()[j*MMAX<D>()+m];
    int b = N2<D>()[j*MMAX<D>()+m];
    float va = (a >= 0) ? in[a] : 0.f;
    float vb = (b >= 0) ? in[b] : 0.f;
    out[m] = in[m] + 0.5f*(va + vb);
}
template<int D>
__global__ void sliceNormK(float alpha, int p){
    int i = blockIdx.x*blockDim.x + threadIdx.x;
    if (i >= NPIX) return;
    const float* nb = p ? G.nbuf1 : G.nbuf0;
    const int*   os = OS<D>(); const float* ws = WSp<D>();
    float s = 0.f;
    #pragma unroll
    for (int j=0;j<=D;j++) s += ws[i*(D+1)+j] * nb[os[i*(D+1)+j]];
    float* nrm = (D==DBIL) ? G.normB : G.normS;
    nrm[i] = alpha * s + 1e-20f;
}

// ---------------- hot-loop kernels -------------------------------------------
__device__ __forceinline__ float4 f4fma(float4 a, float s, float4 b){
    return make_float4(fmaf(a.x,s,b.x), fmaf(a.y,s,b.y), fmaf(a.z,s,b.z), fmaf(a.w,s,b.w));
}
__device__ __forceinline__ float4 f4add(float4 a, float4 b){
    return make_float4(a.x+b.x, a.y+b.y, a.z+b.z, a.w+b.w);
}

// CSR gather splat: one thread per bilateral lattice row
__global__ void splatCsrBK(){
    int m = blockIdx.x*blockDim.x + threadIdx.x;
    if (m >= G.countB) return;
    int s = G.startB[m], e = s + G.cntB[m];
    float4 a0=make_float4(0,0,0,0), a1=a0, a2=a0, a3=a0, a4=a0, a5=a0;
    for (int k=s;k<e;k++){
        int pix = G.entryPixB[k];
        float w = G.entryWB[k];
        const float4* q = &G.Q[pix*NQ4];
        a0 = f4fma(q[0], w, a0);
        a1 = f4fma(q[1], w, a1);
        a2 = f4fma(q[2], w, a2);
        a3 = f4fma(q[3], w, a3);
        a4 = f4fma(q[4], w, a4);
        a5 = f4fma(q[5], w, a5);
    }
    float4* s0 = &G.bufB0[(size_t)m*SEGW];
    s0[0]=a0; s0[1]=a1; s0[2]=a2;
    float4* s1 = &G.bufB0[(size_t)MBIL*SEGW + (size_t)m*SEGW];
    s1[0]=a3; s1[1]=a4; s1[2]=a5;
}
// CSR gather splat: one thread per spatial lattice row (unsegmented, 6 f4)
__global__ void splatCsrSK(){
    int m = blockIdx.x*blockDim.x + threadIdx.x;
    if (m >= G.countS) return;
    int s = G.startS[m], e = s + G.cntS[m];
    float4 a[NQ4];
    #pragma unroll
    for (int q=0;q<NQ4;q++) a[q]=make_float4(0,0,0,0);
    for (int k=s;k<e;k++){
        int pix = G.entryPixS[k];
        float w = G.entryWS[k];
        const float4* q = &G.Q[pix*NQ4];
        #pragma unroll
        for (int qi=0;qi<NQ4;qi++) a[qi] = f4fma(q[qi], w, a[qi]);
    }
    float4* o = &G.bufS0[(size_t)m*NQ4];
    #pragma unroll
    for (int qi=0;qi<NQ4;qi++) o[qi]=a[qi];
}

// bilateral blur pass on one channel segment (rows of 3 float4s)
__global__ void blurBK(int j, int p, int seg){
    long long tid = (long long)blockIdx.x*blockDim.x + threadIdx.x;
    int M = G.countB;
    int m = (int)(tid / SEGW), q = (int)(tid % SEGW);
    if (m >= M) return;
    size_t base = (size_t)seg*MBIL*SEGW;
    const float4* __restrict__ in  = (p ? G.bufB1 : G.bufB0) + base;
    float4*       __restrict__ out = (p ? G.bufB0 : G.bufB1) + base;
    int a = G.n1B[j*MBIL+m];
    int b = G.n2B[j*MBIL+m];
    float4 self = in[(size_t)m*SEGW+q];
    float4 acc = make_float4(0.f,0.f,0.f,0.f);
    if (a >= 0) acc = in[(size_t)a*SEGW+q];
    if (b >= 0) acc = f4add(acc, in[(size_t)b*SEGW+q]);
    out[(size_t)m*SEGW+q] = f4fma(acc, 0.5f, self);
}

// spatial blur pass (rows of 6 float4s)
__global__ void blurSK(int j, int p){
    long long tid = (long long)blockIdx.x*blockDim.x + threadIdx.x;
    int M = G.countS;
    int m = (int)(tid / NQ4), q = (int)(tid % NQ4);
    if (m >= M) return;
    const float4* __restrict__ in  = p ? G.bufS1 : G.bufS0;
    float4*       __restrict__ out = p ? G.bufS0 : G.bufS1;
    int a = G.n1S[j*MSP+m];
    int b = G.n2S[j*MSP+m];
    float4 self = in[(size_t)m*NQ4+q];
    float4 acc = make_float4(0.f,0.f,0.f,0.f);
    if (a >= 0) acc = in[(size_t)a*NQ4+q];
    if (b >= 0) acc = f4add(acc, in[(size_t)b*NQ4+q]);
    out[(size_t)m*NQ4+q] = f4fma(acc, 0.5f, self);
}

// fused: last bilateral blur pass (j=5) + sliceB + last spatial pass (j=2) +
// sliceS + softmax. One thread per pixel.
__global__ void fusedSliceSoftmaxK(const float* __restrict__ U,
                                   float* __restrict__ out, int writeOut,
                                   float fBmul, float fSmul){
    int i = blockIdx.x*blockDim.x + threadIdx.x;
    if (i >= NPIX) return;

    int   osb[DBIL+1]; float wsb[DBIL+1];
    int   a1b[DBIL+1], a2b[DBIL+1];
    #pragma unroll
    for (int j=0;j<=DBIL;j++){
        osb[j] = G.osB[i*(DBIL+1)+j];
        wsb[j] = G.wsB[i*(DBIL+1)+j];
        a1b[j] = G.n1B[DBIL*MBIL + osb[j]];
        a2b[j] = G.n2B[DBIL*MBIL + osb[j]];
    }
    int   oss[DSP+1]; float wss[DSP+1];
    int   a1s[DSP+1], a2s[DSP+1];
    #pragma unroll
    for (int j=0;j<=DSP;j++){
        oss[j] = G.osS[i*(DSP+1)+j];
        wss[j] = G.wsS[i*(DSP+1)+j];
        a1s[j] = G.n1S[DSP*MSP + oss[j]];
        a2s[j] = G.n2S[DSP*MSP + oss[j]];
    }
    float fB = fBmul / G.normB[i];
    float fS = fSmul / G.normS[i];

    const float4* __restrict__ bB = G.bufB1;  // 5 passes done -> bufB1
    const float4* __restrict__ bS = G.bufS0;  // 2 passes done -> bufS0

    float lg[NCP];
    float mx = -3.4e38f;
    #pragma unroll
    for (int q=0;q<NQ4;q++){
        int seg = (q < SEGW) ? 0 : 1;
        int qq  = q - seg*SEGW;
        size_t base = (size_t)seg*MBIL*SEGW + qq;
        float4 sB = make_float4(0.f,0.f,0.f,0.f);
        #pragma unroll
        for (int j=0;j<=DBIL;j++){
            float4 v = bB[base + (size_t)osb[j]*SEGW];
            float4 nb = make_float4(0.f,0.f,0.f,0.f);
            if (a1b[j] >= 0) nb = bB[base + (size_t)a1b[j]*SEGW];
            if (a2b[j] >= 0) nb = f4add(nb, bB[base + (size_t)a2b[j]*SEGW]);
            v = f4fma(nb, 0.5f, v);
            sB = f4fma(v, wsb[j], sB);
        }
        float4 sS = make_float4(0.f,0.f,0.f,0.f);
        #pragma unroll
        for (int j=0;j<=DSP;j++){
            float4 v = bS[(size_t)oss[j]*NQ4+q];
            float4 nb = make_float4(0.f,0.f,0.f,0.f);
            if (a1s[j] >= 0) nb = bS[(size_t)a1s[j]*NQ4+q];
            if (a2s[j] >= 0) nb = f4add(nb, bS[(size_t)a2s[j]*NQ4+q]);
            v = f4fma(nb, 0.5f, v);
            sS = f4fma(v, wss[j], sS);
        }
        #pragma unroll
        for (int k=0;k<4;k++){
            int ch = q*4+k;
            float m4 = (k==0)?(fB*sB.x+fS*sS.x):(k==1)?(fB*sB.y+fS*sS.y)
                     : (k==2)?(fB*sB.z+fS*sS.z):(fB*sB.w+fS*sS.w);
            float l = (ch < NC) ? (-U[i*NC+ch] + m4) : -3.4e38f;
            lg[q*4+k] = l;
            mx = fmaxf(mx, l);
        }
    }
    float sum = 0.f;
    #pragma unroll
    for (int c=0;c<NCP;c++){
        float e = (lg[c] > -1e37f) ? expf(lg[c]-mx) : 0.f;
        lg[c] = e; sum += e;
    }
    float inv = 1.0f / sum;
    #pragma unroll
    for (int q=0;q<NQ4;q++){
        float4 qv = make_float4(lg[q*4+0]*inv, lg[q*4+1]*inv, lg[q*4+2]*inv, lg[q*4+3]*inv);
        G.Q[i*NQ4+q] = qv;
        if (writeOut){
            int base = q*4;
            float* o = out + (long long)i*NC;
            o[base+0] = qv.x;
            if (base+1 < NC) o[base+1] = qv.y;
            if (base+2 < NC) o[base+2] = qv.z;
            if (base+3 < NC) o[base+3] = qv.w;
        }
    }
}

__global__ void softmax0K(const float* __restrict__ U){
    int i = blockIdx.x*blockDim.x + threadIdx.x;
    if (i >= NPIX) return;
    float t[NC];
    float mx = -3.4e38f;
    #pragma unroll
    for (int c=0;c<NC;c++){
        float l = -U[i*NC+c];
        t[c] = l; mx = fmaxf(mx, l);
    }
    float sum = 0.f;
    #pragma unroll
    for (int c=0;c<NC;c++){ float e = expf(t[c]-mx); t[c]=e; sum += e; }
    float inv = 1.0f / sum;
    float* q = (float*)&G.Q[i*NQ4];
    #pragma unroll
    for (int c=0;c<NC;c++) q[c] = t[c]*inv;
    #pragma unroll
    for (int c=NC;c<NCP;c++) q[c] = 0.f;
}

// ---------------- host -------------------------------------------------------
static inline unsigned int gridFor(long long n, int B){ return (unsigned int)((n + B - 1) / B); }

extern "C" void kernel_launch(void* const* d_in, const int* in_sizes, int n_in,
                              void* d_out, int out_size){
    const float* unary = nullptr;
    const float* image = nullptr;
    for (int k=0;k<n_in;k++){
        if      (in_sizes[k] == NPIX*NC) unary = (const float*)d_in[k];
        else if (in_sizes[k] == NPIX*3)  image = (const float*)d_in[k];
    }
    if (!unary || !image) return;
    float* out = (float*)d_out;
    const int B = 256;

    const float ALPHA_B = 32.0f/33.0f;
    const float ALPHA_S = 0.8f;
    const float WB = 10.0f, WSPA = 3.0f;

    // ---- build lattices ----
    initHashK<DBIL><<<gridFor(HBSZ,B), B>>>();
    buildK<DBIL><<<gridFor(NPIX,B), B>>>(image);
    assignK<DBIL><<<gridFor(HBSZ,B), B>>>();
    osK<DBIL><<<gridFor(NPIX*(DBIL+1),B), B>>>();
    neighK<DBIL><<<gridFor(MBIL,B), B>>>();

    initHashK<DSP><<<gridFor(HSSZ,B), B>>>();
    buildK<DSP><<<gridFor(NPIX,B), B>>>(image);
    assignK<DSP><<<gridFor(HSSZ,B), B>>>();
    osK<DSP><<<gridFor(NPIX*(DSP+1),B), B>>>();
    neighK<DSP><<<gridFor(MSP,B), B>>>();

    // ---- CSR build ----
    zeroCntK<DBIL><<<gridFor(MBIL,B), B>>>();
    countRowsK<DBIL><<<gridFor(NPIX*(DBIL+1),B), B>>>();
    scanAK<DBIL><<<MBIL/256, 256>>>();
    scanBK<DBIL><<<1, 1024>>>();
    scanCK<DBIL><<<MBIL/256, 256>>>();
    fillK<DBIL><<<gridFor(NPIX*(DBIL+1),B), B>>>();

    zeroCntK<DSP><<<gridFor(MSP,B), B>>>();
    countRowsK<DSP><<<gridFor(NPIX*(DSP+1),B), B>>>();
    scanAK<DSP><<<MSP/256, 256>>>();
    scanBK<DSP><<<1, 1024>>>();
    scanCK<DSP><<<MSP/256, 256>>>();
    fillK<DSP><<<gridFor(NPIX*(DSP+1),B), B>>>();

    // ---- norms (filter of ones) ----
    zeroNK<DBIL><<<gridFor(MBIL,B), B>>>();
    splatNK<DBIL><<<gridFor(NPIX,B), B>>>();
    for (int j=0;j<DBIL+1;j++) blurNK<DBIL><<<gridFor(MBIL,B), B>>>(j, j&1);
    sliceNormK<DBIL><<<gridFor(NPIX,B), B>>>(ALPHA_B, (DBIL+1)&1);
    zeroNK<DSP><<<gridFor(MSP,B), B>>>();
    splatNK<DSP><<<gridFor(NPIX,B), B>>>();
    for (int j=0;j<DSP+1;j++) blurNK<DSP><<<gridFor(MSP,B), B>>>(j, j&1);
    sliceNormK<DSP><<<gridFor(NPIX,B), B>>>(ALPHA_S, (DSP+1)&1);

    // ---- Q0 = softmax(-U) ----
    softmax0K<<<gridFor(NPIX,B), B>>>(unary);

    // ---- 5 mean-field iterations ----
    for (int it=0; it<5; ++it){
        splatCsrBK<<<gridFor(MBIL,B), B>>>();
        splatCsrSK<<<gridFor(MSP,B), B>>>();

        // bilateral: 5 passes per segment (j=5 fused into slice)
        for (int seg=0; seg<2; ++seg)
            for (int j=0;j<DBIL;j++)
                blurBK<<<gridFor((long long)MBIL*SEGW,B), B>>>(j, j&1, seg);
        // spatial: 2 passes (j=2 fused into slice)
        for (int j=0;j<DSP;j++)
            blurSK<<<gridFor((long long)MSP*NQ4,B), B>>>(j, j&1);

        fusedSliceSoftmaxK<<<gridFor(NPIX,B), B>>>(
            unary, out, (it==4) ? 1 : 0,
            WB*ALPHA_B, WSPA*ALPHA_S);
    }
}

// round 4
// speedup vs baseline: 2.0242x; 1.2543x over previous
#include <cuda_runtime.h>
#include <cstdint>
#include <math.h>

// ----------------------------------------------------------------------------
// DenseCRF mean-field, permutohedral lattice. Round 4:
//  - blur passes fused in PAIRS (2-hop expansion, guarded gathers): 6 bilateral
//    passes -> 3 super-passes; 3 spatial -> 1 super + 1 single
//  - slice un-fused (6+3 row gathers/pixel), CSR gather splat kept
//  - bilateral buffers stay channel-segmented (48B rows) for L2 residency
// ----------------------------------------------------------------------------

#define HH 320
#define WW 320
#define NPIX (HH*WW)                 // 102400
#define NC 21
#define NCP 24
#define NQ4 6                        // float4s per pixel Q row
#define SEGW 3                       // float4s per bilateral segment row
#define DBIL 5
#define DSP 2
#define MBIL (NPIX*(DBIL+1))         // 614400
#define MSP  (NPIX*(DSP+1))          // 307200
#define HBSZ (1u<<21)
#define HSSZ (1u<<20)
#define EMPTYK 0xFFFFFFFFFFFFFFFFULL

struct Globals {
    unsigned long long hkeyB[HBSZ];
    int                hidxB[HBSZ];
    unsigned long long hkeyS[HSSZ];
    int                hidxS[HSSZ];
    int countB, countS, pad_[2];
    unsigned long long ukeyB[MBIL];
    unsigned long long ukeyS[MSP];
    unsigned long long pkB[NPIX*(DBIL+1)];
    unsigned long long pkS[NPIX*(DSP+1)];
    int   osB[NPIX*(DBIL+1)];
    float wsB[NPIX*(DBIL+1)];
    int   osS[NPIX*(DSP+1)];
    float wsS[NPIX*(DSP+1)];
    int n1B[(DBIL+1)*MBIL];
    int n2B[(DBIL+1)*MBIL];
    int n1S[(DSP+1)*MSP];
    int n2S[(DSP+1)*MSP];
    // CSR (pixel entries per lattice row)
    int   cntB[MBIL], startB[MBIL], fillB[MBIL];
    int   cntS[MSP],  startS[MSP],  fillS[MSP];
    int   bsumB[4096], bsumS[4096];
    int   entryPixB[NPIX*(DBIL+1)];
    float entryWB [NPIX*(DBIL+1)];
    int   entryPixS[NPIX*(DSP+1)];
    float entryWS [NPIX*(DSP+1)];
    // blur buffers: bilateral segmented [2][MBIL][3], spatial [MSP][6]
    float4 bufB0[2ll*MBIL*SEGW];
    float4 bufB1[2ll*MBIL*SEGW];
    float4 bufS0[(long long)MSP*NQ4];
    float4 bufS1[(long long)MSP*NQ4];
    float nbuf0[MBIL];
    float nbuf1[MBIL];
    float normB[NPIX];
    float normS[NPIX];
    float4 Q[NPIX*NQ4];
};
__device__ Globals G;

// ---------------- selectors --------------------------------------------------
template<int D> __device__ __forceinline__ unsigned long long* HK()   { return (D==DBIL)? G.hkeyB : G.hkeyS; }
template<int D> __device__ __forceinline__ int*                HI()   { return (D==DBIL)? G.hidxB : G.hidxS; }
template<int D> __device__ __forceinline__ int*                CNTp() { return (D==DBIL)? &G.countB : &G.countS; }
template<int D> __device__ __forceinline__ unsigned long long* UK()   { return (D==DBIL)? G.ukeyB : G.ukeyS; }
template<int D> __device__ __forceinline__ unsigned long long* PK()   { return (D==DBIL)? G.pkB : G.pkS; }
template<int D> __device__ __forceinline__ int*                OS()   { return (D==DBIL)? G.osB : G.osS; }
template<int D> __device__ __forceinline__ float*              WSp()  { return (D==DBIL)? G.wsB : G.wsS; }
template<int D> __device__ __forceinline__ int*                N1()   { return (D==DBIL)? G.n1B : G.n1S; }
template<int D> __device__ __forceinline__ int*                N2()   { return (D==DBIL)? G.n2B : G.n2S; }
template<int D> __device__ __forceinline__ int*                RCNT() { return (D==DBIL)? G.cntB : G.cntS; }
template<int D> __device__ __forceinline__ int*                RST()  { return (D==DBIL)? G.startB : G.startS; }
template<int D> __device__ __forceinline__ int*                RFIL() { return (D==DBIL)? G.fillB : G.fillS; }
template<int D> __device__ __forceinline__ int*                BSUM() { return (D==DBIL)? G.bsumB : G.bsumS; }
template<int D> __device__ __forceinline__ int*                EPIX() { return (D==DBIL)? G.entryPixB : G.entryPixS; }
template<int D> __device__ __forceinline__ float*              EW()   { return (D==DBIL)? G.entryWB : G.entryWS; }
template<int D> __host__ __device__ constexpr unsigned int HMSK(){ return (D==DBIL)? (HBSZ-1u) : (HSSZ-1u); }
template<int D> __host__ __device__ constexpr unsigned int HSZ (){ return (D==DBIL)? HBSZ : HSSZ; }
template<int D> __host__ __device__ constexpr int          MMAX(){ return (D==DBIL)? MBIL : MSP; }

// ---------------- hash -------------------------------------------------------
__device__ __forceinline__ unsigned int hmix(unsigned long long x, unsigned int mask){
    x ^= x >> 33; x *= 0xff51afd7ed558ccdULL;
    x ^= x >> 33; x *= 0xc4ceb9fe1a85ec53ULL;
    x ^= x >> 33;
    return (unsigned int)x & mask;
}
__device__ __forceinline__ void hinsert(unsigned long long* hk, unsigned int mask, unsigned long long key){
    unsigned int s = hmix(key, mask);
    while (true){
        unsigned long long prev = atomicCAS(&hk[s], EMPTYK, key);
        if (prev == EMPTYK || prev == key) return;
        s = (s+1) & mask;
    }
}
__device__ __forceinline__ int hlookup(const unsigned long long* hk, const int* hi,
                                       unsigned int mask, unsigned long long key){
    unsigned int s = hmix(key, mask);
    while (true){
        unsigned long long k = hk[s];
        if (k == key)    return hi[s];
        if (k == EMPTYK) return -1;
        s = (s+1) & mask;
    }
}

// ---------------- lattice build ----------------------------------------------
template<int D>
__global__ void initHashK(){
    unsigned int s = blockIdx.x*blockDim.x + threadIdx.x;
    if (s < HSZ<D>()) HK<D>()[s] = EMPTYK;
    if (s == 0) *CNTp<D>() = 0;
}

template<int D>
__global__ void buildK(const float* __restrict__ image){
    int i = blockIdx.x*blockDim.x + threadIdx.x;
    if (i >= NPIX) return;
    float f[D];
    float x = (float)(i % WW), y = (float)(i / WW);
    if constexpr (D == DBIL){
        f[0] = x / 80.0f;  f[1] = y / 80.0f;
        f[2] = image[i*3+0] / 13.0f;
        f[3] = image[i*3+1] / 13.0f;
        f[4] = image[i*3+2] / 13.0f;
    } else {
        f[0] = x / 3.0f;   f[1] = y / 3.0f;
    }
    float cf[D];
    #pragma unroll
    for (int k=0;k<D;k++){
        double sc = sqrt(2.0/3.0) * (double)(D+1) / sqrt((double)((k+1)*(k+2)));
        cf[k] = f[k] * (float)sc;
    }
    float suf[D];
    { float s=0.f; for (int k=D-1;k>=0;k--){ s += cf[k]; suf[k]=s; } }
    float el[D+1];
    el[0] = suf[0];
    #pragma unroll
    for (int k=1;k<=D;k++){
        float t = (k<D) ? suf[k] : 0.0f;
        el[k] = t - (float)k * cf[k-1];
    }
    const float down = 1.0f/(float)(D+1);
    float rem0[D+1]; int rank[D+1]; int ssum=0;
    #pragma unroll
    for (int k=0;k<=D;k++){
        float rd = rintf(el[k]*down);
        rem0[k] = rd * (float)(D+1);
        ssum += (int)rd;
    }
    float diff[D+1];
    #pragma unroll
    for (int k=0;k<=D;k++) diff[k] = el[k] - rem0[k];
    #pragma unroll
    for (int a=0;a<=D;a++){
        int r = 0;
        #pragma unroll
        for (int b=0;b<=D;b++)
            if (diff[b] > diff[a] || (diff[b] == diff[a] && b < a)) r++;
        rank[a] = r + ssum;
    }
    #pragma unroll
    for (int k=0;k<=D;k++){
        if (rank[k] < 0)      { rank[k] += D+1; rem0[k] += (float)(D+1); }
        else if (rank[k] > D) { rank[k] -= D+1; rem0[k] -= (float)(D+1); }
    }
    float bb[D+2];
    #pragma unroll
    for (int k=0;k<D+2;k++) bb[k]=0.f;
    #pragma unroll
    for (int k=0;k<=D;k++){
        float v = (el[k]-rem0[k]) * down;
        bb[D   - rank[k]] += v;
        bb[D+1 - rank[k]] -= v;
    }
    bb[0] += 1.0f + bb[D+1];
    int key0[D];
    #pragma unroll
    for (int k=0;k<D;k++) key0[k] = (int)lrintf(rem0[k]);
    unsigned long long* hk = HK<D>();
    const unsigned int mask = HMSK<D>();
    #pragma unroll
    for (int r=0;r<=D;r++){
        unsigned long long pk = 0;
        #pragma unroll
        for (int k=0;k<D;k++){
            int canon = (rank[k] < D+1-r) ? r : r-(D+1);
            pk |= ((unsigned long long)(unsigned int)(key0[k]+canon+2048) & 0xFFFULL) << (12*k);
        }
        WSp<D>()[i*(D+1)+r] = bb[r];
        PK<D>()[i*(D+1)+r]  = pk;
        hinsert(hk, mask, pk);
    }
}

template<int D>
__global__ void assignK(){
    unsigned int s = blockIdx.x*blockDim.x + threadIdx.x;
    if (s >= HSZ<D>()) return;
    unsigned long long k = HK<D>()[s];
    if (k != EMPTYK){
        int idx = atomicAdd(CNTp<D>(), 1);
        HI<D>()[s] = idx;
        UK<D>()[idx] = k;
    }
}

template<int D>
__global__ void osK(){
    int tid = blockIdx.x*blockDim.x + threadIdx.x;
    if (tid >= NPIX*(D+1)) return;
    OS<D>()[tid] = hlookup(HK<D>(), HI<D>(), HMSK<D>(), PK<D>()[tid]);
}

template<int D>
__global__ void neighK(){
    int m = blockIdx.x*blockDim.x + threadIdx.x;
    if (m >= *CNTp<D>()) return;
    unsigned long long k = UK<D>()[m];
    int c[D];
    #pragma unroll
    for (int t=0;t<D;t++) c[t] = (int)((k >> (12*t)) & 0xFFF) - 2048;
    unsigned long long* hk = HK<D>(); int* hi = HI<D>();
    const unsigned int mask = HMSK<D>();
    #pragma unroll
    for (int j=0;j<=D;j++){
        unsigned long long p1=0, p2=0;
        #pragma unroll
        for (int t=0;t<D;t++){
            int a1 = c[t]-1 + ((t==j)?(D+1):0);
            int a2 = c[t]+1 - ((t==j)?(D+1):0);
            p1 |= ((unsigned long long)(unsigned int)(a1+2048) & 0xFFFULL) << (12*t);
            p2 |= ((unsigned long long)(unsigned int)(a2+2048) & 0xFFFULL) << (12*t);
        }
        N1<D>()[j*MMAX<D>()+m] = hlookup(hk, hi, mask, p1);
        N2<D>()[j*MMAX<D>()+m] = hlookup(hk, hi, mask, p2);
    }
}

// ---------------- CSR build --------------------------------------------------
template<int D>
__global__ void zeroCntK(){
    int m = blockIdx.x*blockDim.x + threadIdx.x;
    if (m < MMAX<D>()) RCNT<D>()[m] = 0;
}
template<int D>
__global__ void countRowsK(){
    int t = blockIdx.x*blockDim.x + threadIdx.x;
    if (t >= NPIX*(D+1)) return;
    atomicAdd(&RCNT<D>()[OS<D>()[t]], 1);
}
template<int D>
__global__ void scanAK(){
    __shared__ int sh[256];
    int t = threadIdx.x;
    int g = blockIdx.x*256 + t;
    int v = (g < MMAX<D>()) ? RCNT<D>()[g] : 0;
    sh[t] = v; __syncthreads();
    #pragma unroll
    for (int o=1;o<256;o<<=1){
        int x = (t>=o) ? sh[t-o] : 0;
        __syncthreads();
        sh[t] += x;
        __syncthreads();
    }
    if (g < MMAX<D>()) RST<D>()[g] = sh[t] - v;
    if (t == 255) BSUM<D>()[blockIdx.x] = sh[255];
}
template<int D>
__global__ void scanBK(){
    __shared__ int sh[1024];
    const int nb = MMAX<D>() / 256;
    int t = threadIdx.x;
    int carry = 0;
    for (int base=0; base<nb; base+=1024){
        int v = (base+t < nb) ? BSUM<D>()[base+t] : 0;
        sh[t] = v; __syncthreads();
        for (int o=1;o<1024;o<<=1){
            int x = (t>=o) ? sh[t-o] : 0;
            __syncthreads();
            sh[t] += x;
            __syncthreads();
        }
        int tot = sh[1023];
        if (base+t < nb) BSUM<D>()[base+t] = sh[t] - v + carry;
        __syncthreads();
        carry += tot;
    }
}
template<int D>
__global__ void scanCK(){
    int g = blockIdx.x*256 + threadIdx.x;
    if (g >= MMAX<D>()) return;
    int s = RST<D>()[g] + BSUM<D>()[g >> 8];
    RST<D>()[g]  = s;
    RFIL<D>()[g] = s;
}
template<int D>
__global__ void fillK(){
    int t = blockIdx.x*blockDim.x + threadIdx.x;
    if (t >= NPIX*(D+1)) return;
    int m = OS<D>()[t];
    int p = atomicAdd(&RFIL<D>()[m], 1);
    EPIX<D>()[p] = t / (D+1);
    EW<D>()[p]   = WSp<D>()[t];
}

// ---------------- norm filter (scalar, one-time) -----------------------------
template<int D>
__global__ void zeroNK(){
    int tid = blockIdx.x*blockDim.x + threadIdx.x;
    if (tid < *CNTp<D>()) G.nbuf0[tid] = 0.f;
}
template<int D>
__global__ void splatNK(){
    int i = blockIdx.x*blockDim.x + threadIdx.x;
    if (i >= NPIX) return;
    const int* os = OS<D>(); const float* ws = WSp<D>();
    #pragma unroll
    for (int j=0;j<=D;j++)
        atomicAdd(&G.nbuf0[os[i*(D+1)+j]], ws[i*(D+1)+j]);
}
template<int D>
__global__ void blurNK(int j, int p){
    int m = blockIdx.x*blockDim.x + threadIdx.x;
    if (m >= *CNTp<D>()) return;
    const float* in = p ? G.nbuf1 : G.nbuf0;
    float*      out = p ? G.nbuf0 : G.nbuf1;
    int a = N1<D>()[j*MMAX<D>()+m];
    int b = N2<D>()[j*MMAX<D>()+m];
    float va = (a >= 0) ? in[a] : 0.f;
    float vb = (b >= 0) ? in[b] : 0.f;
    out[m] = in[m] + 0.5f*(va + vb);
}
template<int D>
__global__ void sliceNormK(float alpha, int p){
    int i = blockIdx.x*blockDim.x + threadIdx.x;
    if (i >= NPIX) return;
    const float* nb = p ? G.nbuf1 : G.nbuf0;
    const int*   os = OS<D>(); const float* ws = WSp<D>();
    float s = 0.f;
    #pragma unroll
    for (int j=0;j<=D;j++) s += ws[i*(D+1)+j] * nb[os[i*(D+1)+j]];
    float* nrm = (D==DBIL) ? G.normB : G.normS;
    nrm[i] = alpha * s + 1e-20f;
}

// ---------------- hot-loop kernels -------------------------------------------
__device__ __forceinline__ float4 f4fma(float4 a, float s, float4 b){
    return make_float4(fmaf(a.x,s,b.x), fmaf(a.y,s,b.y), fmaf(a.z,s,b.z), fmaf(a.w,s,b.w));
}
__device__ __forceinline__ float4 f4add(float4 a, float4 b){
    return make_float4(a.x+b.x, a.y+b.y, a.z+b.z, a.w+b.w);
}

// CSR gather splat: one thread per bilateral lattice row
__global__ void splatCsrBK(){
    int m = blockIdx.x*blockDim.x + threadIdx.x;
    if (m >= G.countB) return;
    int s = G.startB[m], e = s + G.cntB[m];
    float4 a0=make_float4(0,0,0,0), a1=a0, a2=a0, a3=a0, a4=a0, a5=a0;
    for (int k=s;k<e;k++){
        int pix = G.entryPixB[k];
        float w = G.entryWB[k];
        const float4* q = &G.Q[pix*NQ4];
        a0 = f4fma(q[0], w, a0);
        a1 = f4fma(q[1], w, a1);
        a2 = f4fma(q[2], w, a2);
        a3 = f4fma(q[3], w, a3);
        a4 = f4fma(q[4], w, a4);
        a5 = f4fma(q[5], w, a5);
    }
    float4* s0 = &G.bufB0[(size_t)m*SEGW];
    s0[0]=a0; s0[1]=a1; s0[2]=a2;
    float4* s1 = &G.bufB0[(size_t)MBIL*SEGW + (size_t)m*SEGW];
    s1[0]=a3; s1[1]=a4; s1[2]=a5;
}
// CSR gather splat: one thread per spatial lattice row (unsegmented, 6 f4)
__global__ void splatCsrSK(){
    int m = blockIdx.x*blockDim.x + threadIdx.x;
    if (m >= G.countS) return;
    int s = G.startS[m], e = s + G.cntS[m];
    float4 a[NQ4];
    #pragma unroll
    for (int q=0;q<NQ4;q++) a[q]=make_float4(0,0,0,0);
    for (int k=s;k<e;k++){
        int pix = G.entryPixS[k];
        float w = G.entryWS[k];
        const float4* q = &G.Q[pix*NQ4];
        #pragma unroll
        for (int qi=0;qi<NQ4;qi++) a[qi] = f4fma(q[qi], w, a[qi]);
    }
    float4* o = &G.bufS0[(size_t)m*NQ4];
    #pragma unroll
    for (int qi=0;qi<NQ4;qi++) o[qi]=a[qi];
}

// fused PAIR of bilateral blur passes (j1 then j2) on one channel segment.
// out[m] = o1[m] + 0.5*(o1[B1]+o1[B2]),  o1[x] = in[x] + 0.5*(in[n1j1 x]+in[n2j1 x])
__global__ void blur2BK(int j1, int j2, int p, int seg){
    long long tid = (long long)blockIdx.x*blockDim.x + threadIdx.x;
    int M = G.countB;
    int m = (int)(tid / SEGW), q = (int)(tid % SEGW);
    if (m >= M) return;
    size_t base = (size_t)seg*MBIL*SEGW;
    const float4* __restrict__ in  = (p ? G.bufB1 : G.bufB0) + base;
    float4*       __restrict__ out = (p ? G.bufB0 : G.bufB1) + base;
    const int* __restrict__ n1a = G.n1B + (size_t)j1*MBIL;
    const int* __restrict__ n2a = G.n2B + (size_t)j1*MBIL;
    const int* __restrict__ n1b = G.n1B + (size_t)j2*MBIL;
    const int* __restrict__ n2b = G.n2B + (size_t)j2*MBIL;

    int A1 = n1a[m], A2 = n2a[m];
    int B1 = n1b[m], B2 = n2b[m];

    float4 r = in[(size_t)m*SEGW+q];
    {
        float4 acc = make_float4(0,0,0,0);
        if (A1 >= 0) acc = in[(size_t)A1*SEGW+q];
        if (A2 >= 0) acc = f4add(acc, in[(size_t)A2*SEGW+q]);
        r = f4fma(acc, 0.5f, r);                        // o1[m]
    }
    float4 accB = make_float4(0,0,0,0);
    if (B1 >= 0){
        float4 t = in[(size_t)B1*SEGW+q];
        int c1 = n1a[B1], c2 = n2a[B1];
        float4 cc = make_float4(0,0,0,0);
        if (c1 >= 0) cc = in[(size_t)c1*SEGW+q];
        if (c2 >= 0) cc = f4add(cc, in[(size_t)c2*SEGW+q]);
        accB = f4fma(cc, 0.5f, t);                      // o1[B1]
    }
    if (B2 >= 0){
        float4 t = in[(size_t)B2*SEGW+q];
        int c1 = n1a[B2], c2 = n2a[B2];
        float4 cc = make_float4(0,0,0,0);
        if (c1 >= 0) cc = in[(size_t)c1*SEGW+q];
        if (c2 >= 0) cc = f4add(cc, in[(size_t)c2*SEGW+q]);
        accB = f4add(accB, f4fma(cc, 0.5f, t));         // + o1[B2]
    }
    out[(size_t)m*SEGW+q] = f4fma(accB, 0.5f, r);
}

// fused PAIR of spatial blur passes (rows of 6 float4s)
__global__ void blur2SK(int j1, int j2, int p){
    long long tid = (long long)blockIdx.x*blockDim.x + threadIdx.x;
    int M = G.countS;
    int m = (int)(tid / NQ4), q = (int)(tid % NQ4);
    if (m >= M) return;
    const float4* __restrict__ in  = p ? G.bufS1 : G.bufS0;
    float4*       __restrict__ out = p ? G.bufS0 : G.bufS1;
    const int* __restrict__ n1a = G.n1S + (size_t)j1*MSP;
    const int* __restrict__ n2a = G.n2S + (size_t)j1*MSP;
    const int* __restrict__ n1b = G.n1S + (size_t)j2*MSP;
    const int* __restrict__ n2b = G.n2S + (size_t)j2*MSP;

    int A1 = n1a[m], A2 = n2a[m];
    int B1 = n1b[m], B2 = n2b[m];

    float4 r = in[(size_t)m*NQ4+q];
    {
        float4 acc = make_float4(0,0,0,0);
        if (A1 >= 0) acc = in[(size_t)A1*NQ4+q];
        if (A2 >= 0) acc = f4add(acc, in[(size_t)A2*NQ4+q]);
        r = f4fma(acc, 0.5f, r);
    }
    float4 accB = make_float4(0,0,0,0);
    if (B1 >= 0){
        float4 t = in[(size_t)B1*NQ4+q];
        int c1 = n1a[B1], c2 = n2a[B1];
        float4 cc = make_float4(0,0,0,0);
        if (c1 >= 0) cc = in[(size_t)c1*NQ4+q];
        if (c2 >= 0) cc = f4add(cc, in[(size_t)c2*NQ4+q]);
        accB = f4fma(cc, 0.5f, t);
    }
    if (B2 >= 0){
        float4 t = in[(size_t)B2*NQ4+q];
        int c1 = n1a[B2], c2 = n2a[B2];
        float4 cc = make_float4(0,0,0,0);
        if (c1 >= 0) cc = in[(size_t)c1*NQ4+q];
        if (c2 >= 0) cc = f4add(cc, in[(size_t)c2*NQ4+q]);
        accB = f4add(accB, f4fma(cc, 0.5f, t));
    }
    out[(size_t)m*NQ4+q] = f4fma(accB, 0.5f, r);
}

// single spatial blur pass (for the odd 3rd pass)
__global__ void blurSK(int j, int p){
    long long tid = (long long)blockIdx.x*blockDim.x + threadIdx.x;
    int M = G.countS;
    int m = (int)(tid / NQ4), q = (int)(tid % NQ4);
    if (m >= M) return;
    const float4* __restrict__ in  = p ? G.bufS1 : G.bufS0;
    float4*       __restrict__ out = p ? G.bufS0 : G.bufS1;
    int a = G.n1S[j*MSP+m];
    int b = G.n2S[j*MSP+m];
    float4 self = in[(size_t)m*NQ4+q];
    float4 acc = make_float4(0.f,0.f,0.f,0.f);
    if (a >= 0) acc = in[(size_t)a*NQ4+q];
    if (b >= 0) acc = f4add(acc, in[(size_t)b*NQ4+q]);
    out[(size_t)m*NQ4+q] = f4fma(acc, 0.5f, self);
}

// plain slice (6 bilateral rows from segmented bufB1, 3 spatial rows from
// bufS0) + softmax. One thread per pixel.
__global__ void sliceSoftmaxK(const float* __restrict__ U,
                              float* __restrict__ out, int writeOut,
                              float fBmul, float fSmul){
    int i = blockIdx.x*blockDim.x + threadIdx.x;
    if (i >= NPIX) return;

    int   osb[DBIL+1]; float wsb[DBIL+1];
    #pragma unroll
    for (int j=0;j<=DBIL;j++){
        osb[j] = G.osB[i*(DBIL+1)+j];
        wsb[j] = G.wsB[i*(DBIL+1)+j];
    }
    int   oss[DSP+1]; float wss[DSP+1];
    #pragma unroll
    for (int j=0;j<=DSP;j++){
        oss[j] = G.osS[i*(DSP+1)+j];
        wss[j] = G.wsS[i*(DSP+1)+j];
    }
    float fB = fBmul / G.normB[i];
    float fS = fSmul / G.normS[i];

    const float4* __restrict__ bB = G.bufB1;  // 3 super-passes end in bufB1
    const float4* __restrict__ bS = G.bufS0;  // super + single end in bufS0

    float lg[NCP];
    float mx = -3.4e38f;
    #pragma unroll
    for (int q=0;q<NQ4;q++){
        int seg = (q < SEGW) ? 0 : 1;
        int qq  = q - seg*SEGW;
        size_t base = (size_t)seg*MBIL*SEGW + qq;
        float4 sB = make_float4(0.f,0.f,0.f,0.f);
        #pragma unroll
        for (int j=0;j<=DBIL;j++)
            sB = f4fma(bB[base + (size_t)osb[j]*SEGW], wsb[j], sB);
        float4 sS = make_float4(0.f,0.f,0.f,0.f);
        #pragma unroll
        for (int j=0;j<=DSP;j++)
            sS = f4fma(bS[(size_t)oss[j]*NQ4+q], wss[j], sS);
        #pragma unroll
        for (int k=0;k<4;k++){
            int ch = q*4+k;
            float m4 = (k==0)?(fB*sB.x+fS*sS.x):(k==1)?(fB*sB.y+fS*sS.y)
                     : (k==2)?(fB*sB.z+fS*sS.z):(fB*sB.w+fS*sS.w);
            float l = (ch < NC) ? (-U[i*NC+ch] + m4) : -3.4e38f;
            lg[q*4+k] = l;
            mx = fmaxf(mx, l);
        }
    }
    float sum = 0.f;
    #pragma unroll
    for (int c=0;c<NCP;c++){
        float e = (lg[c] > -1e37f) ? expf(lg[c]-mx) : 0.f;
        lg[c] = e; sum += e;
    }
    float inv = 1.0f / sum;
    #pragma unroll
    for (int q=0;q<NQ4;q++){
        float4 qv = make_float4(lg[q*4+0]*inv, lg[q*4+1]*inv, lg[q*4+2]*inv, lg[q*4+3]*inv);
        G.Q[i*NQ4+q] = qv;
        if (writeOut){
            int base = q*4;
            float* o = out + (long long)i*NC;
            o[base+0] = qv.x;
            if (base+1 < NC) o[base+1] = qv.y;
            if (base+2 < NC) o[base+2] = qv.z;
            if (base+3 < NC) o[base+3] = qv.w;
        }
    }
}

__global__ void softmax0K(const float* __restrict__ U){
    int i = blockIdx.x*blockDim.x + threadIdx.x;
    if (i >= NPIX) return;
    float t[NC];
    float mx = -3.4e38f;
    #pragma unroll
    for (int c=0;c<NC;c++){
        float l = -U[i*NC+c];
        t[c] = l; mx = fmaxf(mx, l);
    }
    float sum = 0.f;
    #pragma unroll
    for (int c=0;c<NC;c++){ float e = expf(t[c]-mx); t[c]=e; sum += e; }
    float inv = 1.0f / sum;
    float* q = (float*)&G.Q[i*NQ4];
    #pragma unroll
    for (int c=0;c<NC;c++) q[c] = t[c]*inv;
    #pragma unroll
    for (int c=NC;c<NCP;c++) q[c] = 0.f;
}

// ---------------- host -------------------------------------------------------
static inline unsigned int gridFor(long long n, int B){ return (unsigned int)((n + B - 1) / B); }

extern "C" void kernel_launch(void* const* d_in, const int* in_sizes, int n_in,
                              void* d_out, int out_size){
    const float* unary = nullptr;
    const float* image = nullptr;
    for (int k=0;k<n_in;k++){
        if      (in_sizes[k] == NPIX*NC) unary = (const float*)d_in[k];
        else if (in_sizes[k] == NPIX*3)  image = (const float*)d_in[k];
    }
    if (!unary || !image) return;
    float* out = (float*)d_out;
    const int B = 256;

    const float ALPHA_B = 32.0f/33.0f;
    const float ALPHA_S = 0.8f;
    const float WB = 10.0f, WSPA = 3.0f;

    // ---- build lattices ----
    initHashK<DBIL><<<gridFor(HBSZ,B), B>>>();
    buildK<DBIL><<<gridFor(NPIX,B), B>>>(image);
    assignK<DBIL><<<gridFor(HBSZ,B), B>>>();
    osK<DBIL><<<gridFor(NPIX*(DBIL+1),B), B>>>();
    neighK<DBIL><<<gridFor(MBIL,B), B>>>();

    initHashK<DSP><<<gridFor(HSSZ,B), B>>>();
    buildK<DSP><<<gridFor(NPIX,B), B>>>(image);
    assignK<DSP><<<gridFor(HSSZ,B), B>>>();
    osK<DSP><<<gridFor(NPIX*(DSP+1),B), B>>>();
    neighK<DSP><<<gridFor(MSP,B), B>>>();

    // ---- CSR build ----
    zeroCntK<DBIL><<<gridFor(MBIL,B), B>>>();
    countRowsK<DBIL><<<gridFor(NPIX*(DBIL+1),B), B>>>();
    scanAK<DBIL><<<MBIL/256, 256>>>();
    scanBK<DBIL><<<1, 1024>>>();
    scanCK<DBIL><<<MBIL/256, 256>>>();
    fillK<DBIL><<<gridFor(NPIX*(DBIL+1),B), B>>>();

    zeroCntK<DSP><<<gridFor(MSP,B), B>>>();
    countRowsK<DSP><<<gridFor(NPIX*(DSP+1),B), B>>>();
    scanAK<DSP><<<MSP/256, 256>>>();
    scanBK<DSP><<<1, 1024>>>();
    scanCK<DSP><<<MSP/256, 256>>>();
    fillK<DSP><<<gridFor(NPIX*(DSP+1),B), B>>>();

    // ---- norms (filter of ones) ----
    zeroNK<DBIL><<<gridFor(MBIL,B), B>>>();
    splatNK<DBIL><<<gridFor(NPIX,B), B>>>();
    for (int j=0;j<DBIL+1;j++) blurNK<DBIL><<<gridFor(MBIL,B), B>>>(j, j&1);
    sliceNormK<DBIL><<<gridFor(NPIX,B), B>>>(ALPHA_B, (DBIL+1)&1);
    zeroNK<DSP><<<gridFor(MSP,B), B>>>();
    splatNK<DSP><<<gridFor(NPIX,B), B>>>();
    for (int j=0;j<DSP+1;j++) blurNK<DSP><<<gridFor(MSP,B), B>>>(j, j&1);
    sliceNormK<DSP><<<gridFor(NPIX,B), B>>>(ALPHA_S, (DSP+1)&1);

    // ---- Q0 = softmax(-U) ----
    softmax0K<<<gridFor(NPIX,B), B>>>(unary);

    // ---- 5 mean-field iterations ----
    for (int it=0; it<5; ++it){
        splatCsrBK<<<gridFor(MBIL,B), B>>>();
        splatCsrSK<<<gridFor(MSP,B), B>>>();

        // bilateral: 3 super-passes per segment; parity 0->1->0->1
        for (int seg=0; seg<2; ++seg){
            blur2BK<<<gridFor((long long)MBIL*SEGW,B), B>>>(0, 1, 0, seg);
            blur2BK<<<gridFor((long long)MBIL*SEGW,B), B>>>(2, 3, 1, seg);
            blur2BK<<<gridFor((long long)MBIL*SEGW,B), B>>>(4, 5, 0, seg);
        }
        // spatial: super-pass (0,1): S0->S1; single pass 2: S1->S0
        blur2SK<<<gridFor((long long)MSP*NQ4,B), B>>>(0, 1, 0);
        blurSK <<<gridFor((long long)MSP*NQ4,B), B>>>(2, 1);

        sliceSoftmaxK<<<gridFor(NPIX,B), B>>>(
            unary, out, (it==4) ? 1 : 0,
            WB*ALPHA_B, WSPA*ALPHA_S);
    }
}